// round 14
// baseline (speedup 1.0000x reference)
#include <cuda_runtime.h>
#include <math.h>
#include <stdint.h>

// ---------------------------------------------------------------------------
// Problem constants
// ---------------------------------------------------------------------------
#define NN 4096          // nodes
#define DIN 256          // input dim
#define ED 512           // quantum dim
#define NHEAD 8
#define HD 64
#define MASKW 128        // 4096/32 words per row

#define NEG_INF (__int_as_float(0xff800000))

// ---------------------------------------------------------------------------
// Scratch (device globals; no allocation allowed)
// ---------------------------------------------------------------------------
__device__ float    g_Q0[(size_t)NN * ED];
__device__ float    g_K0[(size_t)NN * ED];
__device__ float    g_QKV[(size_t)3 * NN * ED];   // Qfinal, Kfinal, V
__device__ float    g_qkv2[(size_t)3 * NN * ED];  // q, k, v after in_proj (tf32-RN bits)
__device__ float    g_o[(size_t)NN * ED];
__device__ float    g_bioT[(size_t)ED * ED];
__device__ unsigned g_mask[(size_t)NN * MASKW];
__device__ float    g_rowent[NN];

// ---------------------------------------------------------------------------
// Helpers
// ---------------------------------------------------------------------------
__device__ __forceinline__ float warp_red_sum(float v) {
#pragma unroll
    for (int o = 16; o; o >>= 1) v += __shfl_xor_sync(0xffffffffu, v, o);
    return v;
}
__device__ __forceinline__ float warp_red_max(float v) {
#pragma unroll
    for (int o = 16; o; o >>= 1) v = fmaxf(v, __shfl_xor_sync(0xffffffffu, v, o));
    return v;
}

__device__ __forceinline__ uint32_t f2tf32(float x) {
    uint32_t u;
    asm("cvt.rna.tf32.f32 %0, %1;" : "=r"(u) : "f"(x));
    return u;
}

__device__ __forceinline__ void mma8(float* c, const uint32_t* a, const uint32_t* b) {
    asm volatile(
        "mma.sync.aligned.m16n8k8.row.col.f32.tf32.tf32.f32 "
        "{%0,%1,%2,%3}, {%4,%5,%6,%7}, {%8,%9}, {%0,%1,%2,%3};"
        : "+f"(c[0]), "+f"(c[1]), "+f"(c[2]), "+f"(c[3])
        : "r"(a[0]), "r"(a[1]), "r"(a[2]), "r"(a[3]), "r"(b[0]), "r"(b[1]));
}

__device__ __forceinline__ void cp_async16(uint32_t saddr, const void* gaddr) {
    asm volatile("cp.async.cg.shared.global [%0], [%1], 16;" :: "r"(saddr), "l"(gaddr));
}
#define CP_COMMIT() asm volatile("cp.async.commit_group;" ::: "memory")
#define CP_WAIT0()  asm volatile("cp.async.wait_group 0;" ::: "memory")

// ---------------------------------------------------------------------------
// Mask build
// ---------------------------------------------------------------------------
__global__ void zero_mask_kernel(unsigned* __restrict__ m) {
    m[(size_t)blockIdx.x * 1024 + threadIdx.x] = 0u;
}

__global__ void build_mask_kernel(const int* __restrict__ ei, int ne,
                                  unsigned* __restrict__ m) {
    int idx = blockIdx.x * blockDim.x + threadIdx.x;
    if (idx < ne) {
        int r = ei[idx];
        int c = ei[ne + idx];
        atomicOr(&m[(size_t)r * MASKW + (c >> 5)], 1u << (c & 31));
    }
}

// ---------------------------------------------------------------------------
// 512x512 transpose (bio -> bioT)
// ---------------------------------------------------------------------------
__global__ void transpose512_kernel(const float* __restrict__ in, float* __restrict__ out) {
    __shared__ float tile[32][33];
    int bx = blockIdx.x * 32, by = blockIdx.y * 32;
    int tx = threadIdx.x, ty = threadIdx.y;
#pragma unroll
    for (int j = 0; j < 32; j += 8)
        tile[ty + j][tx] = in[(size_t)(by + ty + j) * ED + bx + tx];
    __syncthreads();
#pragma unroll
    for (int j = 0; j < 32; j += 8)
        out[(size_t)(bx + ty + j) * ED + by + tx] = tile[tx][ty + j];
}

// ---------------------------------------------------------------------------
// fp32 SGEMM (NT), exact: C[M,N] = A[M,K] * B[N,K]^T  (+ epilogue)
// Q/K chain only (zero precision budget for atan2-phase).
// 64x128 tile, 4x8 microtile (32 accum regs) -> ~80 regs/thread ->
// 2-3 CTA/SM co-residency (R10 showed 145 regs blocked the 2nd CTA).
// z-batched: blockIdx.z selects {A0,B0,C0,bias0} / {A1,B1,C1,bias1}.
// ---------------------------------------------------------------------------
#define BM2 64
#define BN2 128
#define BK 16

enum { EPI_BIAS = 0, EPI_CE = 1, EPI_MASK = 2 };

template <int EPI>
__global__ void __launch_bounds__(256, 2)
sgemm_nt2(const float* __restrict__ A0, const float* __restrict__ B0,
          float* __restrict__ C0, const float* __restrict__ bias0,
          const float* __restrict__ A1, const float* __restrict__ B1,
          float* __restrict__ C1, const float* __restrict__ bias1,
          int M, int N, int K,
          const int* __restrict__ ct,
          const float* __restrict__ cemb)
{
    const float* A    = blockIdx.z ? A1 : A0;
    const float* B    = blockIdx.z ? B1 : B0;
    float*       C    = blockIdx.z ? C1 : C0;
    const float* bias = blockIdx.z ? bias1 : bias0;

    __shared__ float As[2][BK][BM2];
    __shared__ float Bs[2][BK][BN2];

    const int tid = threadIdx.x;
    const int tx = tid & 15, ty = tid >> 4;
    const int bm = blockIdx.y * BM2, bn = blockIdx.x * BN2;

    const int arow = tid >> 2;            // 0..63
    const int ac4  = (tid & 3) * 4;       // 0,4,8,12

    float acc[4][8];
#pragma unroll
    for (int i = 0; i < 4; ++i)
#pragma unroll
        for (int j = 0; j < 8; ++j) acc[i][j] = 0.f;

    float4 pa, pb[2];

    auto ldg = [&](int k0) {
        pa = *(const float4*)(A + (size_t)(bm + arow) * K + k0 + ac4);
#pragma unroll
        for (int t = 0; t < 2; ++t) {
            int row = arow + t * 64;
            pb[t] = *(const float4*)(B + (size_t)(bn + row) * K + k0 + ac4);
        }
    };
    auto sts = [&](int st) {
        As[st][ac4 + 0][arow] = pa.x; As[st][ac4 + 1][arow] = pa.y;
        As[st][ac4 + 2][arow] = pa.z; As[st][ac4 + 3][arow] = pa.w;
#pragma unroll
        for (int t = 0; t < 2; ++t) {
            int row = arow + t * 64;
            Bs[st][ac4 + 0][row] = pb[t].x; Bs[st][ac4 + 1][row] = pb[t].y;
            Bs[st][ac4 + 2][row] = pb[t].z; Bs[st][ac4 + 3][row] = pb[t].w;
        }
    };

    ldg(0);
    sts(0);
    __syncthreads();

    const int nk = K / BK;
    int st = 0;
    for (int kt = 0; kt < nk; ++kt) {
        if (kt + 1 < nk) ldg((kt + 1) * BK);
#pragma unroll
        for (int kk = 0; kk < BK; ++kk) {
            float4 a = *(const float4*)&As[st][kk][ty * 4];
            float4 b0 = *(const float4*)&Bs[st][kk][tx * 8];
            float4 b1 = *(const float4*)&Bs[st][kk][tx * 8 + 4];
            float av[4] = {a.x, a.y, a.z, a.w};
            float bv[8] = {b0.x, b0.y, b0.z, b0.w, b1.x, b1.y, b1.z, b1.w};
#pragma unroll
            for (int i = 0; i < 4; ++i)
#pragma unroll
                for (int j = 0; j < 8; ++j)
                    acc[i][j] += av[i] * bv[j];
        }
        if (kt + 1 < nk) sts(st ^ 1);
        __syncthreads();
        st ^= 1;
    }

#pragma unroll
    for (int i = 0; i < 4; ++i) {
        int gm = bm + ty * 4 + i;
#pragma unroll
        for (int j = 0; j < 8; ++j) {
            int gn = bn + tx * 8 + j;
            float v = acc[i][j];
            if (EPI == EPI_BIAS) {
                v += bias[gn];
            } else {
                v += 0.1f * cemb[(size_t)ct[gm] * N + gn];
            }
            C[(size_t)gm * N + gn] = v;
        }
    }
}

// ---------------------------------------------------------------------------
// tf32 tensor-core GEMM (NT):  C[M,N] = A[M,K] * B[N,K]^T  (+ epilogue)
// SPLIT=true: 3xTF32 (near-fp32). SPLIT=false: single tf32, double-buffered.
// CVT=true: store f2tf32(result) bits (producer-side RN conversion for the
// flash-MHA consumer, which then cp.asyncs raw bits).
// ---------------------------------------------------------------------------
template <int TBM, int TBN, int EPI, bool SPLIT, bool CVT>
__global__ void __launch_bounds__(256)
gemm_tf32(const float* __restrict__ A, long long sAz,
          const float* __restrict__ B, long long sBz,
          float* __restrict__ C, long long sCz,
          int M, int N, int K,
          const float* __restrict__ bias, long long sbz,
          const int* __restrict__ ct,
          const float* __restrict__ cemb,
          const unsigned* __restrict__ mask,
          float scale)
{
    constexpr int LDA = TBM + 8;
    constexpr int LDB = TBN + 8;
    constexpr int AF4 = (TBM * 16) / (4 * 256);
    constexpr int BF4 = (TBN * 16) / (4 * 256);
    constexpr int WM = TBM / 4, WN = TBN / 2;
    constexpr int MF = WM / 16, NF = WN / 8;
    constexpr int NC = SPLIT ? 2 : 1;
    constexpr int NBUF = SPLIT ? 1 : 2;

    __shared__ uint32_t As[NBUF][NC][16][LDA];
    __shared__ uint32_t Bs[NBUF][NC][16][LDB];

    A += (size_t)blockIdx.z * sAz;
    B += (size_t)blockIdx.z * sBz;
    C += (size_t)blockIdx.z * sCz;
    if (bias) bias += (size_t)blockIdx.z * sbz;

    const int tid = threadIdx.x;
    const int lane = tid & 31, wid = tid >> 5;
    const int wm = wid & 3, wn = wid >> 2;
    const int bm = blockIdx.y * TBM, bn = blockIdx.x * TBN;
    const int lq = lane >> 2, lr = lane & 3;

    float c[MF][NF][4];
#pragma unroll
    for (int i = 0; i < MF; ++i)
#pragma unroll
        for (int j = 0; j < NF; ++j)
#pragma unroll
            for (int r = 0; r < 4; ++r) c[i][j][r] = 0.f;

    float4 pa[AF4], pb[BF4];

    auto store_a = [&](int st) {
#pragma unroll
        for (int t = 0; t < AF4; ++t) {
            int f = tid + t * 256, m = f >> 2, k4 = (f & 3) * 4;
            float xs[4] = {pa[t].x, pa[t].y, pa[t].z, pa[t].w};
#pragma unroll
            for (int e = 0; e < 4; ++e) {
                uint32_t h = f2tf32(xs[e]);
                As[st][0][k4 + e][m] = h;
                if (SPLIT)
                    As[st][1][k4 + e][m] = f2tf32(xs[e] - __uint_as_float(h));
            }
        }
    };
    auto store_b = [&](int st) {
#pragma unroll
        for (int t = 0; t < BF4; ++t) {
            int f = tid + t * 256, n = f >> 2, k4 = (f & 3) * 4;
            float xs[4] = {pb[t].x, pb[t].y, pb[t].z, pb[t].w};
#pragma unroll
            for (int e = 0; e < 4; ++e) {
                uint32_t h = f2tf32(xs[e]);
                Bs[st][0][k4 + e][n] = h;
                if (SPLIT)
                    Bs[st][1][k4 + e][n] = f2tf32(xs[e] - __uint_as_float(h));
            }
        }
    };
    auto load_ab = [&](int k0) {
#pragma unroll
        for (int t = 0; t < AF4; ++t) {
            int f = tid + t * 256;
            pa[t] = *(const float4*)(A + (size_t)(bm + (f >> 2)) * K + k0 + (f & 3) * 4);
        }
#pragma unroll
        for (int t = 0; t < BF4; ++t) {
            int f = tid + t * 256;
            pb[t] = *(const float4*)(B + (size_t)(bn + (f >> 2)) * K + k0 + (f & 3) * 4);
        }
    };
    auto compute = [&](int st) {
#pragma unroll
        for (int ks = 0; ks < 16; ks += 8) {
            uint32_t af[MF][NC][4], bf[NF][NC][2];
#pragma unroll
            for (int i = 0; i < MF; ++i) {
                int m0 = wm * WM + i * 16;
#pragma unroll
                for (int cc = 0; cc < NC; ++cc) {
                    af[i][cc][0] = As[st][cc][ks + lr][m0 + lq];
                    af[i][cc][1] = As[st][cc][ks + lr][m0 + lq + 8];
                    af[i][cc][2] = As[st][cc][ks + lr + 4][m0 + lq];
                    af[i][cc][3] = As[st][cc][ks + lr + 4][m0 + lq + 8];
                }
            }
#pragma unroll
            for (int j = 0; j < NF; ++j) {
                int n0 = wn * WN + j * 8;
#pragma unroll
                for (int cc = 0; cc < NC; ++cc) {
                    bf[j][cc][0] = Bs[st][cc][ks + lr][n0 + lq];
                    bf[j][cc][1] = Bs[st][cc][ks + lr + 4][n0 + lq];
                }
            }
#pragma unroll
            for (int i = 0; i < MF; ++i)
#pragma unroll
                for (int j = 0; j < NF; ++j) {
                    mma8(c[i][j], af[i][0], bf[j][0]);
                    if (SPLIT) {
                        mma8(c[i][j], af[i][0], bf[j][1]);
                        mma8(c[i][j], af[i][1], bf[j][0]);
                    }
                }
        }
    };

    const int nk = K >> 4;

    if (!SPLIT) {
        load_ab(0);
        store_a(0); store_b(0);
        __syncthreads();
        int st = 0;
        for (int kt = 0; kt < nk; ++kt) {
            if (kt + 1 < nk) load_ab((kt + 1) << 4);
            compute(st);
            if (kt + 1 < nk) { store_a(st ^ 1); store_b(st ^ 1); }
            __syncthreads();
            st ^= 1;
        }
    } else {
        load_ab(0);
        store_a(0); store_b(0);
        __syncthreads();
        for (int kt = 0; kt < nk; ++kt) {
            if (kt + 1 < nk) load_ab((kt + 1) << 4);
            compute(0);
            __syncthreads();
            if (kt + 1 < nk) {
                store_a(0); store_b(0);
                __syncthreads();
            }
        }
    }

#pragma unroll
    for (int i = 0; i < MF; ++i) {
        int gm = bm + wm * WM + i * 16 + lq;
        int t0 = 0, t1 = 0;
        if (EPI == EPI_CE) { t0 = ct[gm]; t1 = ct[gm + 8]; }
#pragma unroll
        for (int j = 0; j < NF; ++j) {
            int gn = bn + wn * WN + j * 8 + lr * 2;
            float v00 = c[i][j][0], v01 = c[i][j][1];
            float v10 = c[i][j][2], v11 = c[i][j][3];
            if (EPI == EPI_BIAS) {
                float b0 = bias[gn], b1 = bias[gn + 1];
                v00 += b0; v01 += b1; v10 += b0; v11 += b1;
            } else if (EPI == EPI_CE) {
                v00 += 0.1f * cemb[(size_t)t0 * N + gn];
                v01 += 0.1f * cemb[(size_t)t0 * N + gn + 1];
                v10 += 0.1f * cemb[(size_t)t1 * N + gn];
                v11 += 0.1f * cemb[(size_t)t1 * N + gn + 1];
            } else {
                unsigned w0 = mask[(size_t)gm * MASKW + (gn >> 5)];
                unsigned w1 = mask[(size_t)(gm + 8) * MASKW + (gn >> 5)];
                v00 = ((w0 >> (gn & 31)) & 1u) ? v00 * scale : -1e9f;
                v01 = ((w0 >> ((gn + 1) & 31)) & 1u) ? v01 * scale : -1e9f;
                v10 = ((w1 >> (gn & 31)) & 1u) ? v10 * scale : -1e9f;
                v11 = ((w1 >> ((gn + 1) & 31)) & 1u) ? v11 * scale : -1e9f;
            }
            if (CVT) {
                v00 = __uint_as_float(f2tf32(v00));
                v01 = __uint_as_float(f2tf32(v01));
                v10 = __uint_as_float(f2tf32(v10));
                v11 = __uint_as_float(f2tf32(v11));
            }
            float2 r0 = {v00, v01}, r1 = {v10, v11};
            *(float2*)(C + (size_t)gm * N + gn) = r0;
            *(float2*)(C + (size_t)(gm + 8) * N + gn) = r1;
        }
    }
}

// ---------------------------------------------------------------------------
// phase = atan2(K, Q) elementwise
// ---------------------------------------------------------------------------
__global__ void phase_kernel(const float* __restrict__ Q, const float* __restrict__ K,
                             float* __restrict__ phase) {
    size_t i = (size_t)blockIdx.x * blockDim.x + threadIdx.x;
    phase[i] = atan2f(K[i], Q[i]);
}

// ---------------------------------------------------------------------------
// Row softmax over masked scores (in-place on attn region) + per-row entropy
// ---------------------------------------------------------------------------
__global__ void __launch_bounds__(256)
softmax_row_kernel(float* __restrict__ attn, float* __restrict__ row_ent) {
    __shared__ float red[8];
    __shared__ float bval;
    const int tid = threadIdx.x;
    const int wid = tid >> 5, lane = tid & 31;
    float* p = attn + (size_t)blockIdx.x * NN;

    float4 x[4];
#pragma unroll
    for (int t = 0; t < 4; ++t)
        x[t] = *(const float4*)(p + t * 1024 + tid * 4);

    float mx = NEG_INF;
#pragma unroll
    for (int t = 0; t < 4; ++t)
        mx = fmaxf(fmaxf(fmaxf(mx, x[t].x), fmaxf(x[t].y, x[t].z)), x[t].w);
    mx = warp_red_max(mx);
    if (lane == 0) red[wid] = mx;
    __syncthreads();
    if (wid == 0) {
        float v = (lane < 8) ? red[lane] : NEG_INF;
        v = warp_red_max(v);
        if (lane == 0) bval = v;
    }
    __syncthreads();
    mx = bval;
    __syncthreads();

    float e[16];
    float s = 0.f;
#pragma unroll
    for (int t = 0; t < 4; ++t) {
        e[t * 4 + 0] = __expf(x[t].x - mx);
        e[t * 4 + 1] = __expf(x[t].y - mx);
        e[t * 4 + 2] = __expf(x[t].z - mx);
        e[t * 4 + 3] = __expf(x[t].w - mx);
        s += e[t * 4 + 0] + e[t * 4 + 1] + e[t * 4 + 2] + e[t * 4 + 3];
    }
    s = warp_red_sum(s);
    if (lane == 0) red[wid] = s;
    __syncthreads();
    if (wid == 0) {
        float v = (lane < 8) ? red[lane] : 0.f;
        v = warp_red_sum(v);
        if (lane == 0) bval = v;
    }
    __syncthreads();
    const float inv = 1.0f / bval;
    __syncthreads();

    float ent = 0.f;
#pragma unroll
    for (int t = 0; t < 4; ++t) {
        float4 r;
        r.x = e[t * 4 + 0] * inv;
        r.y = e[t * 4 + 1] * inv;
        r.z = e[t * 4 + 2] * inv;
        r.w = e[t * 4 + 3] * inv;
        ent += r.x * logf(r.x + 1e-10f) + r.y * logf(r.y + 1e-10f)
             + r.z * logf(r.z + 1e-10f) + r.w * logf(r.w + 1e-10f);
        *(float4*)(p + t * 1024 + tid * 4) = r;
    }
    ent = warp_red_sum(ent);
    if (lane == 0) red[wid] = ent;
    __syncthreads();
    if (wid == 0) {
        float v = (lane < 8) ? red[lane] : 0.f;
        v = warp_red_sum(v);
        if (lane == 0) row_ent[blockIdx.x] = v;
    }
}

__global__ void reduce_entropy_kernel(const float* __restrict__ row_ent,
                                      float* __restrict__ coh) {
    __shared__ float red[32];
    int tid = threadIdx.x, lane = tid & 31, wid = tid >> 5;
    float v = row_ent[tid] + row_ent[tid + 1024] + row_ent[tid + 2048] + row_ent[tid + 3072];
    v = warp_red_sum(v);
    if (lane == 0) red[wid] = v;
    __syncthreads();
    if (wid == 0) {
        float s = red[lane];
        s = warp_red_sum(s);
        if (lane == 0) {
            float entropy = -s;
            *coh = 1.0f - entropy / logf((float)NN);
        }
    }
}

// ---------------------------------------------------------------------------
// Flash MHA on tf32 tensor cores: softmax(q k^T / 8) v, per head.
// v4: inputs (qkv2) are ALREADY RN-tf32 (converted in the in_proj epilogue),
// so K/V cp.async raw bits straight into smem (full pipeline, no CVT cost,
// full RN accuracy). Q scaled by exact 1/8 (tf32-closed). P reuses Q staging.
// 112 KB smem -> 2 CTA/SM -> one wave.
// ---------------------------------------------------------------------------
#define PLD 76
#define KLD 76
#define VLD 72
#define KTS (64 * KLD)
#define VTS (64 * VLD)

__global__ void __launch_bounds__(256, 2)
flash_mha_tf32(const float* __restrict__ q, const float* __restrict__ k,
               const float* __restrict__ v, float* __restrict__ o)
{
    extern __shared__ uint32_t sm[];
    uint32_t* Pn = sm;                    // [128][PLD]  (Q staging, then P)
    uint32_t* Ks = Pn + 128 * PLD;        // [2][64][KLD] RN-tf32 bits
    uint32_t* Vs = Ks + 2 * KTS;          // [2][64][VLD] RN-tf32 bits

    const int tid = threadIdx.x;
    const int lane = tid & 31, wid = tid >> 5;
    const int lq = lane >> 2, lr = lane & 3;
    const int qbase = blockIdx.x * 128;
    const int hoff = blockIdx.y * HD;
    const int m0 = wid * 16;

    const uint32_t ks_base = (uint32_t)__cvta_generic_to_shared(Ks);
    const uint32_t vs_base = (uint32_t)__cvta_generic_to_shared(Vs);

    // Q (already tf32) -> smem staging, scaled by exact 1/8 (exponent shift)
#pragma unroll
    for (int t = 0; t < 8; ++t) {
        int f = tid + t * 256;                  // 0..2047 float4s
        int row = f >> 4, c4 = (f & 15) * 4;
        float4 val = *(const float4*)(q + (size_t)(qbase + row) * ED + hoff + c4);
        Pn[row * PLD + c4 + 0] = __float_as_uint(0.125f * val.x);
        Pn[row * PLD + c4 + 1] = __float_as_uint(0.125f * val.y);
        Pn[row * PLD + c4 + 2] = __float_as_uint(0.125f * val.z);
        Pn[row * PLD + c4 + 3] = __float_as_uint(0.125f * val.w);
    }
    __syncthreads();

    // Q fragments to registers
    uint32_t qa[8][4];
#pragma unroll
    for (int ks = 0; ks < 8; ++ks) {
        qa[ks][0] = Pn[(m0 + lq) * PLD + ks * 8 + lr];
        qa[ks][1] = Pn[(m0 + lq + 8) * PLD + ks * 8 + lr];
        qa[ks][2] = Pn[(m0 + lq) * PLD + ks * 8 + lr + 4];
        qa[ks][3] = Pn[(m0 + lq + 8) * PLD + ks * 8 + lr + 4];
    }

    auto prefetch = [&](int kt, int stg) {
        const float* kg = k + (size_t)(kt * 64) * ED + hoff;
        const float* vg = v + (size_t)(kt * 64) * ED + hoff;
        uint32_t kb = ks_base + (uint32_t)(stg * KTS) * 4u;
        uint32_t vb = vs_base + (uint32_t)(stg * VTS) * 4u;
#pragma unroll
        for (int t = 0; t < 4; ++t) {
            int f = tid + t * 256;              // 0..1023 float4s
            int row = f >> 4, c4 = (f & 15) * 4;
            cp_async16(kb + (uint32_t)(row * KLD + c4) * 4u, kg + (size_t)row * ED + c4);
            cp_async16(vb + (uint32_t)(row * VLD + c4) * 4u, vg + (size_t)row * ED + c4);
        }
    };

    float m_i[2] = {NEG_INF, NEG_INF};
    float l_i[2] = {0.f, 0.f};
    float oacc[8][4];
#pragma unroll
    for (int j = 0; j < 8; ++j)
#pragma unroll
        for (int r = 0; r < 4; ++r) oacc[j][r] = 0.f;

    prefetch(0, 0);
    CP_COMMIT();
    CP_WAIT0();
    __syncthreads();   // stage 0 ready; also orders Q-fragment reads before P writes

    int st = 0;
    for (int kt = 0; kt < NN / 64; ++kt) {
        if (kt + 1 < NN / 64) { prefetch(kt + 1, st ^ 1); CP_COMMIT(); }

        const uint32_t* kb = Ks + st * KTS;
        const uint32_t* vb = Vs + st * VTS;

        // S = Q K^T (scale folded into Q)
        float s[8][4];
#pragma unroll
        for (int j = 0; j < 8; ++j)
#pragma unroll
            for (int r = 0; r < 4; ++r) s[j][r] = 0.f;

#pragma unroll
        for (int ks = 0; ks < 8; ++ks) {
            uint32_t bf[8][2];
#pragma unroll
            for (int j = 0; j < 8; ++j) {
                bf[j][0] = kb[(j * 8 + lq) * KLD + ks * 8 + lr];
                bf[j][1] = kb[(j * 8 + lq) * KLD + ks * 8 + lr + 4];
            }
#pragma unroll
            for (int j = 0; j < 8; ++j)
                mma8(s[j], qa[ks], bf[j]);
        }

        // online softmax; rows lq (r0,r1) and lq+8 (r2,r3)
        float mx0 = NEG_INF, mx1 = NEG_INF;
#pragma unroll
        for (int j = 0; j < 8; ++j) {
            mx0 = fmaxf(mx0, fmaxf(s[j][0], s[j][1]));
            mx1 = fmaxf(mx1, fmaxf(s[j][2], s[j][3]));
        }
        mx0 = fmaxf(mx0, __shfl_xor_sync(0xffffffffu, mx0, 1));
        mx0 = fmaxf(mx0, __shfl_xor_sync(0xffffffffu, mx0, 2));
        mx1 = fmaxf(mx1, __shfl_xor_sync(0xffffffffu, mx1, 1));
        mx1 = fmaxf(mx1, __shfl_xor_sync(0xffffffffu, mx1, 2));

        float mn0 = fmaxf(m_i[0], mx0), mn1 = fmaxf(m_i[1], mx1);
        float c0 = __expf(m_i[0] - mn0), c1 = __expf(m_i[1] - mn1);
        m_i[0] = mn0; m_i[1] = mn1;

        float ls0 = 0.f, ls1 = 0.f;
#pragma unroll
        for (int j = 0; j < 8; ++j) {
            float p0 = __expf(s[j][0] - mn0);
            float p1 = __expf(s[j][1] - mn0);
            float p2 = __expf(s[j][2] - mn1);
            float p3 = __expf(s[j][3] - mn1);
            ls0 += p0 + p1;
            ls1 += p2 + p3;
            Pn[(m0 + lq) * PLD + j * 8 + 2 * lr]     = f2tf32(p0);
            Pn[(m0 + lq) * PLD + j * 8 + 2 * lr + 1] = f2tf32(p1);
            Pn[(m0 + lq + 8) * PLD + j * 8 + 2 * lr]     = f2tf32(p2);
            Pn[(m0 + lq + 8) * PLD + j * 8 + 2 * lr + 1] = f2tf32(p3);
        }
        ls0 += __shfl_xor_sync(0xffffffffu, ls0, 1);
        ls0 += __shfl_xor_sync(0xffffffffu, ls0, 2);
        ls1 += __shfl_xor_sync(0xffffffffu, ls1, 1);
        ls1 += __shfl_xor_sync(0xffffffffu, ls1, 2);
        l_i[0] = l_i[0] * c0 + ls0;
        l_i[1] = l_i[1] * c1 + ls1;

#pragma unroll
        for (int j = 0; j < 8; ++j) {
            oacc[j][0] *= c0; oacc[j][1] *= c0;
            oacc[j][2] *= c1; oacc[j][3] *= c1;
        }
        __syncwarp();

        // O += P V
#pragma unroll
        for (int ks = 0; ks < 8; ++ks) {
            uint32_t pa4[4];
            pa4[0] = Pn[(m0 + lq) * PLD + ks * 8 + lr];
            pa4[1] = Pn[(m0 + lq + 8) * PLD + ks * 8 + lr];
            pa4[2] = Pn[(m0 + lq) * PLD + ks * 8 + lr + 4];
            pa4[3] = Pn[(m0 + lq + 8) * PLD + ks * 8 + lr + 4];
            uint32_t bf[8][2];
#pragma unroll
            for (int j = 0; j < 8; ++j) {
                bf[j][0] = vb[(ks * 8 + lr) * VLD + j * 8 + lq];
                bf[j][1] = vb[(ks * 8 + lr + 4) * VLD + j * 8 + lq];
            }
#pragma unroll
            for (int j = 0; j < 8; ++j)
                mma8(oacc[j], pa4, bf[j]);
        }

        if (kt + 1 < NN / 64) CP_WAIT0();
        __syncthreads();
        st ^= 1;
    }

    // normalize + store
    float inv0 = 1.0f / l_i[0], inv1 = 1.0f / l_i[1];
#pragma unroll
    for (int j = 0; j < 8; ++j) {
        float2 r0 = {oacc[j][0] * inv0, oacc[j][1] * inv0};
        float2 r1 = {oacc[j][2] * inv1, oacc[j][3] * inv1};
        *(float2*)(o + (size_t)(qbase + m0 + lq) * ED + hoff + j * 8 + 2 * lr) = r0;
        *(float2*)(o + (size_t)(qbase + m0 + lq + 8) * ED + hoff + j * 8 + 2 * lr) = r1;
    }
}

// ---------------------------------------------------------------------------
// Host launcher
// ---------------------------------------------------------------------------
extern "C" void kernel_launch(void* const* d_in, const int* in_sizes, int n_in,
                              void* d_out, int out_size)
{
    const float* nf   = (const float*)d_in[0];
    const int*   ei   = (const int*)  d_in[1];
    const int*   ct   = (const int*)  d_in[2];
    const float* Wq   = (const float*)d_in[3];
    const float* bq   = (const float*)d_in[4];
    const float* Wk   = (const float*)d_in[5];
    const float* bk   = (const float*)d_in[6];
    const float* Wv   = (const float*)d_in[7];
    const float* bv   = (const float*)d_in[8];
    const float* bio  = (const float*)d_in[9];
    const float* cemb = (const float*)d_in[10];
    const float* ipw  = (const float*)d_in[11];
    const float* ipb  = (const float*)d_in[12];
    const float* outw = (const float*)d_in[13];
    const float* outb = (const float*)d_in[14];

    float* out      = (float*)d_out;
    float* attended = out;                                    // [4096,512]
    float* attn     = out + (size_t)NN * ED;                  // [4096,4096]
    float* phase    = attn + (size_t)NN * NN;                 // [4096,512]
    float* coh      = phase + (size_t)NN * ED;                // scalar

    const int ne = in_sizes[1] / 2;
    const size_t NS = (size_t)NN * ED;

    float *Q0, *K0, *QKV, *qkv2, *og, *bioT, *rowent;
    unsigned* msk;
    cudaGetSymbolAddress((void**)&Q0,     g_Q0);
    cudaGetSymbolAddress((void**)&K0,     g_K0);
    cudaGetSymbolAddress((void**)&QKV,    g_QKV);
    cudaGetSymbolAddress((void**)&qkv2,   g_qkv2);
    cudaGetSymbolAddress((void**)&og,     g_o);
    cudaGetSymbolAddress((void**)&bioT,   g_bioT);
    cudaGetSymbolAddress((void**)&msk,    g_mask);
    cudaGetSymbolAddress((void**)&rowent, g_rowent);

    // edge mask
    zero_mask_kernel<<<(NN * MASKW) / 1024, 1024>>>(msk);
    build_mask_kernel<<<(ne + 255) / 256, 256>>>(ei, ne, msk);

    // bio^T for Q-side mixing
    transpose512_kernel<<<dim3(16, 16), dim3(32, 8)>>>(bio, bioT);

    // ---- Q/K chain feeding phase: EXACT fp32 (FFMA), 64x128 tiles, z-batched ----
    sgemm_nt2<EPI_BIAS><<<dim3(4, 64, 2), 256>>>(nf, Wq, Q0, bq,
                                                 nf, Wk, K0, bk,
                                                 NN, ED, DIN, nullptr, nullptr);
    sgemm_nt2<EPI_CE><<<dim3(4, 64, 2), 256>>>(Q0, bioT, QKV, nullptr,
                                               K0, bio, QKV + NS, nullptr,
                                               NN, ED, ED, ct, cemb);

    // V projection (3xTF32, feeds only attended)
    gemm_tf32<64, 128, EPI_BIAS, true, false><<<dim3(4, 64), 256>>>(
        nf, 0, Wv, 0, QKV + 2 * NS, 0, NN, ED, DIN,
        bv, 0, nullptr, nullptr, nullptr, 0.f);

    // phase = atan2(Kf, Qf)  (exact inputs)
    phase_kernel<<<(NN * ED) / 1024, 1024>>>(QKV, QKV + NS, phase);

    // masked scores -> attn region (1xTF32):  Qf @ Kf^T / sqrt(512), -1e9 off-edge
    gemm_tf32<128, 128, EPI_MASK, false, false><<<dim3(32, 32), 256>>>(
        QKV, 0, QKV + NS, 0, attn, 0, NN, NN, ED,
        nullptr, 0, nullptr, nullptr, msk, 0.044194173824159216f);

    // row softmax in-place + per-row entropy, then coherence
    softmax_row_kernel<<<NN, 256>>>(attn, rowent);
    reduce_entropy_kernel<<<1, 1024>>>(rowent, coh);

    // in_proj (3xTF32, batched z=3), epilogue stores RN-tf32 bits for flash
    gemm_tf32<64, 128, EPI_BIAS, true, true><<<dim3(4, 64, 3), 256>>>(
        QKV, (long long)NS, ipw, (long long)ED * ED, qkv2, (long long)NS,
        NN, ED, ED, ipb, (long long)ED,
        nullptr, nullptr, nullptr, 0.f);

    // flash MHA per head (tf32 tensor cores, cp.async raw RN bits, 2 CTA/SM)
    const int mha_smem = (128 * PLD + 2 * KTS + 2 * VTS) * 4;   // 114688 B
    cudaFuncSetAttribute(flash_mha_tf32, cudaFuncAttributeMaxDynamicSharedMemorySize, mha_smem);
    flash_mha_tf32<<<dim3(NN / 128, NHEAD), 256, mha_smem>>>(qkv2, qkv2 + NS, qkv2 + 2 * NS, og);

    // output projection (3xTF32)
    gemm_tf32<64, 128, EPI_BIAS, true, false><<<dim3(4, 64), 256>>>(
        og, 0, outw, 0, attended, 0, NN, ED, ED,
        outb, 0, nullptr, nullptr, nullptr, 0.f);
}

// round 15
// speedup vs baseline: 1.0919x; 1.0919x over previous
#include <cuda_runtime.h>
#include <math.h>
#include <stdint.h>

// ---------------------------------------------------------------------------
// Problem constants
// ---------------------------------------------------------------------------
#define NN 4096          // nodes
#define DIN 256          // input dim
#define ED 512           // quantum dim
#define NHEAD 8
#define HD 64
#define MASKW 128        // 4096/32 words per row

#define NEG_INF (__int_as_float(0xff800000))

// ---------------------------------------------------------------------------
// Scratch (device globals; no allocation allowed)
// ---------------------------------------------------------------------------
__device__ float    g_Q0[(size_t)NN * ED];
__device__ float    g_K0[(size_t)NN * ED];
__device__ float    g_QKV[(size_t)3 * NN * ED];   // Qfinal, Kfinal, V
__device__ float    g_qkv2[(size_t)3 * NN * ED];  // q, k, v after in_proj (tf32-RN bits)
__device__ float    g_o[(size_t)NN * ED];
__device__ float    g_bioT[(size_t)ED * ED];
__device__ unsigned g_mask[(size_t)NN * MASKW];
__device__ float    g_rowent[NN];

// ---------------------------------------------------------------------------
// Helpers
// ---------------------------------------------------------------------------
__device__ __forceinline__ float warp_red_sum(float v) {
#pragma unroll
    for (int o = 16; o; o >>= 1) v += __shfl_xor_sync(0xffffffffu, v, o);
    return v;
}
__device__ __forceinline__ float warp_red_max(float v) {
#pragma unroll
    for (int o = 16; o; o >>= 1) v = fmaxf(v, __shfl_xor_sync(0xffffffffu, v, o));
    return v;
}

__device__ __forceinline__ uint32_t f2tf32(float x) {
    uint32_t u;
    asm("cvt.rna.tf32.f32 %0, %1;" : "=r"(u) : "f"(x));
    return u;
}

__device__ __forceinline__ void mma8(float* c, const uint32_t* a, const uint32_t* b) {
    asm volatile(
        "mma.sync.aligned.m16n8k8.row.col.f32.tf32.tf32.f32 "
        "{%0,%1,%2,%3}, {%4,%5,%6,%7}, {%8,%9}, {%0,%1,%2,%3};"
        : "+f"(c[0]), "+f"(c[1]), "+f"(c[2]), "+f"(c[3])
        : "r"(a[0]), "r"(a[1]), "r"(a[2]), "r"(a[3]), "r"(b[0]), "r"(b[1]));
}

__device__ __forceinline__ void cp_async16(uint32_t saddr, const void* gaddr) {
    asm volatile("cp.async.cg.shared.global [%0], [%1], 16;" :: "r"(saddr), "l"(gaddr));
}
#define CP_COMMIT() asm volatile("cp.async.commit_group;" ::: "memory")
#define CP_WAIT0()  asm volatile("cp.async.wait_group 0;" ::: "memory")

// ---------------------------------------------------------------------------
// Mask build
// ---------------------------------------------------------------------------
__global__ void zero_mask_kernel(unsigned* __restrict__ m) {
    m[(size_t)blockIdx.x * 1024 + threadIdx.x] = 0u;
}

__global__ void build_mask_kernel(const int* __restrict__ ei, int ne,
                                  unsigned* __restrict__ m) {
    int idx = blockIdx.x * blockDim.x + threadIdx.x;
    if (idx < ne) {
        int r = ei[idx];
        int c = ei[ne + idx];
        atomicOr(&m[(size_t)r * MASKW + (c >> 5)], 1u << (c & 31));
    }
}

// ---------------------------------------------------------------------------
// 512x512 transpose (bio -> bioT)
// ---------------------------------------------------------------------------
__global__ void transpose512_kernel(const float* __restrict__ in, float* __restrict__ out) {
    __shared__ float tile[32][33];
    int bx = blockIdx.x * 32, by = blockIdx.y * 32;
    int tx = threadIdx.x, ty = threadIdx.y;
#pragma unroll
    for (int j = 0; j < 32; j += 8)
        tile[ty + j][tx] = in[(size_t)(by + ty + j) * ED + bx + tx];
    __syncthreads();
#pragma unroll
    for (int j = 0; j < 32; j += 8)
        out[(size_t)(bx + ty + j) * ED + by + tx] = tile[tx][ty + j];
}

// ---------------------------------------------------------------------------
// fp32 SGEMM (NT), exact: C[M,N] = A[M,K] * B[N,K]^T  (+ epilogue)
// Q/K chain only (zero precision budget for atan2-phase).
// 128x128 tile, 8x8 microtile (1.0 B-of-LDS per FMA — the 64x128 tile's
// 1.5 B/FMA was crossbar-bound at L1=74%), with __launch_bounds__(256,2)
// forcing regs<=128 so TWO CTAs co-reside (R10 showed 145 regs blocked it).
// z-batched: blockIdx.z selects {A0,B0,C0,bias0} / {A1,B1,C1,bias1}.
// ---------------------------------------------------------------------------
#define BM 128
#define BN 128
#define BK 16

enum { EPI_BIAS = 0, EPI_CE = 1, EPI_MASK = 2 };

template <int EPI>
__global__ void __launch_bounds__(256, 2)
sgemm_nt2(const float* __restrict__ A0, const float* __restrict__ B0,
          float* __restrict__ C0, const float* __restrict__ bias0,
          const float* __restrict__ A1, const float* __restrict__ B1,
          float* __restrict__ C1, const float* __restrict__ bias1,
          int M, int N, int K,
          const int* __restrict__ ct,
          const float* __restrict__ cemb)
{
    const float* A    = blockIdx.z ? A1 : A0;
    const float* B    = blockIdx.z ? B1 : B0;
    float*       C    = blockIdx.z ? C1 : C0;
    const float* bias = blockIdx.z ? bias1 : bias0;

    __shared__ float As[2][BK][BM];
    __shared__ float Bs[2][BK][BN];

    const int tid = threadIdx.x;
    const int tx = tid & 15, ty = tid >> 4;
    const int bm = blockIdx.y * BM, bn = blockIdx.x * BN;

    const int lrow = tid >> 2;            // 0..63
    const int lc4  = (tid & 3) * 4;       // 0,4,8,12

    float acc[8][8];
#pragma unroll
    for (int i = 0; i < 8; ++i)
#pragma unroll
        for (int j = 0; j < 8; ++j) acc[i][j] = 0.f;

    float4 pa[2], pb[2];

    auto ldg = [&](int k0) {
#pragma unroll
        for (int t = 0; t < 2; ++t) {
            int row = lrow + t * 64;
            pa[t] = *(const float4*)(A + (size_t)(bm + row) * K + k0 + lc4);
            pb[t] = *(const float4*)(B + (size_t)(bn + row) * K + k0 + lc4);
        }
    };
    auto sts = [&](int st) {
#pragma unroll
        for (int t = 0; t < 2; ++t) {
            int row = lrow + t * 64;
            As[st][lc4 + 0][row] = pa[t].x; As[st][lc4 + 1][row] = pa[t].y;
            As[st][lc4 + 2][row] = pa[t].z; As[st][lc4 + 3][row] = pa[t].w;
            Bs[st][lc4 + 0][row] = pb[t].x; Bs[st][lc4 + 1][row] = pb[t].y;
            Bs[st][lc4 + 2][row] = pb[t].z; Bs[st][lc4 + 3][row] = pb[t].w;
        }
    };

    ldg(0);
    sts(0);
    __syncthreads();

    const int nk = K / BK;
    int st = 0;
    for (int kt = 0; kt < nk; ++kt) {
        if (kt + 1 < nk) ldg((kt + 1) * BK);
#pragma unroll
        for (int kk = 0; kk < BK; ++kk) {
            float4 a0 = *(const float4*)&As[st][kk][ty * 8];
            float4 a1 = *(const float4*)&As[st][kk][ty * 8 + 4];
            float4 b0 = *(const float4*)&Bs[st][kk][tx * 8];
            float4 b1 = *(const float4*)&Bs[st][kk][tx * 8 + 4];
            float av[8] = {a0.x, a0.y, a0.z, a0.w, a1.x, a1.y, a1.z, a1.w};
            float bv[8] = {b0.x, b0.y, b0.z, b0.w, b1.x, b1.y, b1.z, b1.w};
#pragma unroll
            for (int i = 0; i < 8; ++i)
#pragma unroll
                for (int j = 0; j < 8; ++j)
                    acc[i][j] += av[i] * bv[j];
        }
        if (kt + 1 < nk) sts(st ^ 1);
        __syncthreads();
        st ^= 1;
    }

#pragma unroll
    for (int i = 0; i < 8; ++i) {
        int gm = bm + ty * 8 + i;
#pragma unroll
        for (int j = 0; j < 8; ++j) {
            int gn = bn + tx * 8 + j;
            float v = acc[i][j];
            if (EPI == EPI_BIAS) {
                v += bias[gn];
            } else {
                v += 0.1f * cemb[(size_t)ct[gm] * N + gn];
            }
            C[(size_t)gm * N + gn] = v;
        }
    }
}

// ---------------------------------------------------------------------------
// tf32 tensor-core GEMM (NT):  C[M,N] = A[M,K] * B[N,K]^T  (+ epilogue)
// SPLIT=true: 3xTF32 (near-fp32). SPLIT=false: single tf32, double-buffered.
// CVT=true: store f2tf32(result) bits (producer-side RN conversion for the
// flash-MHA consumer, which then cp.asyncs raw bits).
// ---------------------------------------------------------------------------
template <int TBM, int TBN, int EPI, bool SPLIT, bool CVT>
__global__ void __launch_bounds__(256)
gemm_tf32(const float* __restrict__ A, long long sAz,
          const float* __restrict__ B, long long sBz,
          float* __restrict__ C, long long sCz,
          int M, int N, int K,
          const float* __restrict__ bias, long long sbz,
          const int* __restrict__ ct,
          const float* __restrict__ cemb,
          const unsigned* __restrict__ mask,
          float scale)
{
    constexpr int LDA = TBM + 8;
    constexpr int LDB = TBN + 8;
    constexpr int AF4 = (TBM * 16) / (4 * 256);
    constexpr int BF4 = (TBN * 16) / (4 * 256);
    constexpr int WM = TBM / 4, WN = TBN / 2;
    constexpr int MF = WM / 16, NF = WN / 8;
    constexpr int NC = SPLIT ? 2 : 1;
    constexpr int NBUF = SPLIT ? 1 : 2;

    __shared__ uint32_t As[NBUF][NC][16][LDA];
    __shared__ uint32_t Bs[NBUF][NC][16][LDB];

    A += (size_t)blockIdx.z * sAz;
    B += (size_t)blockIdx.z * sBz;
    C += (size_t)blockIdx.z * sCz;
    if (bias) bias += (size_t)blockIdx.z * sbz;

    const int tid = threadIdx.x;
    const int lane = tid & 31, wid = tid >> 5;
    const int wm = wid & 3, wn = wid >> 2;
    const int bm = blockIdx.y * TBM, bn = blockIdx.x * TBN;
    const int lq = lane >> 2, lr = lane & 3;

    float c[MF][NF][4];
#pragma unroll
    for (int i = 0; i < MF; ++i)
#pragma unroll
        for (int j = 0; j < NF; ++j)
#pragma unroll
            for (int r = 0; r < 4; ++r) c[i][j][r] = 0.f;

    float4 pa[AF4], pb[BF4];

    auto store_a = [&](int st) {
#pragma unroll
        for (int t = 0; t < AF4; ++t) {
            int f = tid + t * 256, m = f >> 2, k4 = (f & 3) * 4;
            float xs[4] = {pa[t].x, pa[t].y, pa[t].z, pa[t].w};
#pragma unroll
            for (int e = 0; e < 4; ++e) {
                uint32_t h = f2tf32(xs[e]);
                As[st][0][k4 + e][m] = h;
                if (SPLIT)
                    As[st][1][k4 + e][m] = f2tf32(xs[e] - __uint_as_float(h));
            }
        }
    };
    auto store_b = [&](int st) {
#pragma unroll
        for (int t = 0; t < BF4; ++t) {
            int f = tid + t * 256, n = f >> 2, k4 = (f & 3) * 4;
            float xs[4] = {pb[t].x, pb[t].y, pb[t].z, pb[t].w};
#pragma unroll
            for (int e = 0; e < 4; ++e) {
                uint32_t h = f2tf32(xs[e]);
                Bs[st][0][k4 + e][n] = h;
                if (SPLIT)
                    Bs[st][1][k4 + e][n] = f2tf32(xs[e] - __uint_as_float(h));
            }
        }
    };
    auto load_ab = [&](int k0) {
#pragma unroll
        for (int t = 0; t < AF4; ++t) {
            int f = tid + t * 256;
            pa[t] = *(const float4*)(A + (size_t)(bm + (f >> 2)) * K + k0 + (f & 3) * 4);
        }
#pragma unroll
        for (int t = 0; t < BF4; ++t) {
            int f = tid + t * 256;
            pb[t] = *(const float4*)(B + (size_t)(bn + (f >> 2)) * K + k0 + (f & 3) * 4);
        }
    };
    auto compute = [&](int st) {
#pragma unroll
        for (int ks = 0; ks < 16; ks += 8) {
            uint32_t af[MF][NC][4], bf[NF][NC][2];
#pragma unroll
            for (int i = 0; i < MF; ++i) {
                int m0 = wm * WM + i * 16;
#pragma unroll
                for (int cc = 0; cc < NC; ++cc) {
                    af[i][cc][0] = As[st][cc][ks + lr][m0 + lq];
                    af[i][cc][1] = As[st][cc][ks + lr][m0 + lq + 8];
                    af[i][cc][2] = As[st][cc][ks + lr + 4][m0 + lq];
                    af[i][cc][3] = As[st][cc][ks + lr + 4][m0 + lq + 8];
                }
            }
#pragma unroll
            for (int j = 0; j < NF; ++j) {
                int n0 = wn * WN + j * 8;
#pragma unroll
                for (int cc = 0; cc < NC; ++cc) {
                    bf[j][cc][0] = Bs[st][cc][ks + lr][n0 + lq];
                    bf[j][cc][1] = Bs[st][cc][ks + lr + 4][n0 + lq];
                }
            }
#pragma unroll
            for (int i = 0; i < MF; ++i)
#pragma unroll
                for (int j = 0; j < NF; ++j) {
                    mma8(c[i][j], af[i][0], bf[j][0]);
                    if (SPLIT) {
                        mma8(c[i][j], af[i][0], bf[j][1]);
                        mma8(c[i][j], af[i][1], bf[j][0]);
                    }
                }
        }
    };

    const int nk = K >> 4;

    if (!SPLIT) {
        load_ab(0);
        store_a(0); store_b(0);
        __syncthreads();
        int st = 0;
        for (int kt = 0; kt < nk; ++kt) {
            if (kt + 1 < nk) load_ab((kt + 1) << 4);
            compute(st);
            if (kt + 1 < nk) { store_a(st ^ 1); store_b(st ^ 1); }
            __syncthreads();
            st ^= 1;
        }
    } else {
        load_ab(0);
        store_a(0); store_b(0);
        __syncthreads();
        for (int kt = 0; kt < nk; ++kt) {
            if (kt + 1 < nk) load_ab((kt + 1) << 4);
            compute(0);
            __syncthreads();
            if (kt + 1 < nk) {
                store_a(0); store_b(0);
                __syncthreads();
            }
        }
    }

#pragma unroll
    for (int i = 0; i < MF; ++i) {
        int gm = bm + wm * WM + i * 16 + lq;
        int t0 = 0, t1 = 0;
        if (EPI == EPI_CE) { t0 = ct[gm]; t1 = ct[gm + 8]; }
#pragma unroll
        for (int j = 0; j < NF; ++j) {
            int gn = bn + wn * WN + j * 8 + lr * 2;
            float v00 = c[i][j][0], v01 = c[i][j][1];
            float v10 = c[i][j][2], v11 = c[i][j][3];
            if (EPI == EPI_BIAS) {
                float b0 = bias[gn], b1 = bias[gn + 1];
                v00 += b0; v01 += b1; v10 += b0; v11 += b1;
            } else if (EPI == EPI_CE) {
                v00 += 0.1f * cemb[(size_t)t0 * N + gn];
                v01 += 0.1f * cemb[(size_t)t0 * N + gn + 1];
                v10 += 0.1f * cemb[(size_t)t1 * N + gn];
                v11 += 0.1f * cemb[(size_t)t1 * N + gn + 1];
            } else {
                unsigned w0 = mask[(size_t)gm * MASKW + (gn >> 5)];
                unsigned w1 = mask[(size_t)(gm + 8) * MASKW + (gn >> 5)];
                v00 = ((w0 >> (gn & 31)) & 1u) ? v00 * scale : -1e9f;
                v01 = ((w0 >> ((gn + 1) & 31)) & 1u) ? v01 * scale : -1e9f;
                v10 = ((w1 >> (gn & 31)) & 1u) ? v10 * scale : -1e9f;
                v11 = ((w1 >> ((gn + 1) & 31)) & 1u) ? v11 * scale : -1e9f;
            }
            if (CVT) {
                v00 = __uint_as_float(f2tf32(v00));
                v01 = __uint_as_float(f2tf32(v01));
                v10 = __uint_as_float(f2tf32(v10));
                v11 = __uint_as_float(f2tf32(v11));
            }
            float2 r0 = {v00, v01}, r1 = {v10, v11};
            *(float2*)(C + (size_t)gm * N + gn) = r0;
            *(float2*)(C + (size_t)(gm + 8) * N + gn) = r1;
        }
    }
}

// ---------------------------------------------------------------------------
// phase = atan2(K, Q) elementwise
// ---------------------------------------------------------------------------
__global__ void phase_kernel(const float* __restrict__ Q, const float* __restrict__ K,
                             float* __restrict__ phase) {
    size_t i = (size_t)blockIdx.x * blockDim.x + threadIdx.x;
    phase[i] = atan2f(K[i], Q[i]);
}

// ---------------------------------------------------------------------------
// Row softmax over masked scores (in-place on attn region) + per-row entropy
// ---------------------------------------------------------------------------
__global__ void __launch_bounds__(256)
softmax_row_kernel(float* __restrict__ attn, float* __restrict__ row_ent) {
    __shared__ float red[8];
    __shared__ float bval;
    const int tid = threadIdx.x;
    const int wid = tid >> 5, lane = tid & 31;
    float* p = attn + (size_t)blockIdx.x * NN;

    float4 x[4];
#pragma unroll
    for (int t = 0; t < 4; ++t)
        x[t] = *(const float4*)(p + t * 1024 + tid * 4);

    float mx = NEG_INF;
#pragma unroll
    for (int t = 0; t < 4; ++t)
        mx = fmaxf(fmaxf(fmaxf(mx, x[t].x), fmaxf(x[t].y, x[t].z)), x[t].w);
    mx = warp_red_max(mx);
    if (lane == 0) red[wid] = mx;
    __syncthreads();
    if (wid == 0) {
        float v = (lane < 8) ? red[lane] : NEG_INF;
        v = warp_red_max(v);
        if (lane == 0) bval = v;
    }
    __syncthreads();
    mx = bval;
    __syncthreads();

    float e[16];
    float s = 0.f;
#pragma unroll
    for (int t = 0; t < 4; ++t) {
        e[t * 4 + 0] = __expf(x[t].x - mx);
        e[t * 4 + 1] = __expf(x[t].y - mx);
        e[t * 4 + 2] = __expf(x[t].z - mx);
        e[t * 4 + 3] = __expf(x[t].w - mx);
        s += e[t * 4 + 0] + e[t * 4 + 1] + e[t * 4 + 2] + e[t * 4 + 3];
    }
    s = warp_red_sum(s);
    if (lane == 0) red[wid] = s;
    __syncthreads();
    if (wid == 0) {
        float v = (lane < 8) ? red[lane] : 0.f;
        v = warp_red_sum(v);
        if (lane == 0) bval = v;
    }
    __syncthreads();
    const float inv = 1.0f / bval;
    __syncthreads();

    float ent = 0.f;
#pragma unroll
    for (int t = 0; t < 4; ++t) {
        float4 r;
        r.x = e[t * 4 + 0] * inv;
        r.y = e[t * 4 + 1] * inv;
        r.z = e[t * 4 + 2] * inv;
        r.w = e[t * 4 + 3] * inv;
        ent += r.x * logf(r.x + 1e-10f) + r.y * logf(r.y + 1e-10f)
             + r.z * logf(r.z + 1e-10f) + r.w * logf(r.w + 1e-10f);
        *(float4*)(p + t * 1024 + tid * 4) = r;
    }
    ent = warp_red_sum(ent);
    if (lane == 0) red[wid] = ent;
    __syncthreads();
    if (wid == 0) {
        float v = (lane < 8) ? red[lane] : 0.f;
        v = warp_red_sum(v);
        if (lane == 0) row_ent[blockIdx.x] = v;
    }
}

__global__ void reduce_entropy_kernel(const float* __restrict__ row_ent,
                                      float* __restrict__ coh) {
    __shared__ float red[32];
    int tid = threadIdx.x, lane = tid & 31, wid = tid >> 5;
    float v = row_ent[tid] + row_ent[tid + 1024] + row_ent[tid + 2048] + row_ent[tid + 3072];
    v = warp_red_sum(v);
    if (lane == 0) red[wid] = v;
    __syncthreads();
    if (wid == 0) {
        float s = red[lane];
        s = warp_red_sum(s);
        if (lane == 0) {
            float entropy = -s;
            *coh = 1.0f - entropy / logf((float)NN);
        }
    }
}

// ---------------------------------------------------------------------------
// Flash MHA on tf32 tensor cores: softmax(q k^T / 8) v, per head.
// v4: inputs (qkv2) are ALREADY RN-tf32 (converted in the in_proj epilogue),
// so K/V cp.async raw bits straight into smem (full pipeline, no CVT cost,
// full RN accuracy). Q scaled by exact 1/8 (tf32-closed). P reuses Q staging.
// 112 KB smem -> 2 CTA/SM -> one wave.
// ---------------------------------------------------------------------------
#define PLD 76
#define KLD 76
#define VLD 72
#define KTS (64 * KLD)
#define VTS (64 * VLD)

__global__ void __launch_bounds__(256, 2)
flash_mha_tf32(const float* __restrict__ q, const float* __restrict__ k,
               const float* __restrict__ v, float* __restrict__ o)
{
    extern __shared__ uint32_t sm[];
    uint32_t* Pn = sm;                    // [128][PLD]  (Q staging, then P)
    uint32_t* Ks = Pn + 128 * PLD;        // [2][64][KLD] RN-tf32 bits
    uint32_t* Vs = Ks + 2 * KTS;          // [2][64][VLD] RN-tf32 bits

    const int tid = threadIdx.x;
    const int lane = tid & 31, wid = tid >> 5;
    const int lq = lane >> 2, lr = lane & 3;
    const int qbase = blockIdx.x * 128;
    const int hoff = blockIdx.y * HD;
    const int m0 = wid * 16;

    const uint32_t ks_base = (uint32_t)__cvta_generic_to_shared(Ks);
    const uint32_t vs_base = (uint32_t)__cvta_generic_to_shared(Vs);

    // Q (already tf32) -> smem staging, scaled by exact 1/8 (exponent shift)
#pragma unroll
    for (int t = 0; t < 8; ++t) {
        int f = tid + t * 256;                  // 0..2047 float4s
        int row = f >> 4, c4 = (f & 15) * 4;
        float4 val = *(const float4*)(q + (size_t)(qbase + row) * ED + hoff + c4);
        Pn[row * PLD + c4 + 0] = __float_as_uint(0.125f * val.x);
        Pn[row * PLD + c4 + 1] = __float_as_uint(0.125f * val.y);
        Pn[row * PLD + c4 + 2] = __float_as_uint(0.125f * val.z);
        Pn[row * PLD + c4 + 3] = __float_as_uint(0.125f * val.w);
    }
    __syncthreads();

    // Q fragments to registers
    uint32_t qa[8][4];
#pragma unroll
    for (int ks = 0; ks < 8; ++ks) {
        qa[ks][0] = Pn[(m0 + lq) * PLD + ks * 8 + lr];
        qa[ks][1] = Pn[(m0 + lq + 8) * PLD + ks * 8 + lr];
        qa[ks][2] = Pn[(m0 + lq) * PLD + ks * 8 + lr + 4];
        qa[ks][3] = Pn[(m0 + lq + 8) * PLD + ks * 8 + lr + 4];
    }

    auto prefetch = [&](int kt, int stg) {
        const float* kg = k + (size_t)(kt * 64) * ED + hoff;
        const float* vg = v + (size_t)(kt * 64) * ED + hoff;
        uint32_t kb = ks_base + (uint32_t)(stg * KTS) * 4u;
        uint32_t vb = vs_base + (uint32_t)(stg * VTS) * 4u;
#pragma unroll
        for (int t = 0; t < 4; ++t) {
            int f = tid + t * 256;              // 0..1023 float4s
            int row = f >> 4, c4 = (f & 15) * 4;
            cp_async16(kb + (uint32_t)(row * KLD + c4) * 4u, kg + (size_t)row * ED + c4);
            cp_async16(vb + (uint32_t)(row * VLD + c4) * 4u, vg + (size_t)row * ED + c4);
        }
    };

    float m_i[2] = {NEG_INF, NEG_INF};
    float l_i[2] = {0.f, 0.f};
    float oacc[8][4];
#pragma unroll
    for (int j = 0; j < 8; ++j)
#pragma unroll
        for (int r = 0; r < 4; ++r) oacc[j][r] = 0.f;

    prefetch(0, 0);
    CP_COMMIT();
    CP_WAIT0();
    __syncthreads();   // stage 0 ready; also orders Q-fragment reads before P writes

    int st = 0;
    for (int kt = 0; kt < NN / 64; ++kt) {
        if (kt + 1 < NN / 64) { prefetch(kt + 1, st ^ 1); CP_COMMIT(); }

        const uint32_t* kb = Ks + st * KTS;
        const uint32_t* vb = Vs + st * VTS;

        // S = Q K^T (scale folded into Q)
        float s[8][4];
#pragma unroll
        for (int j = 0; j < 8; ++j)
#pragma unroll
            for (int r = 0; r < 4; ++r) s[j][r] = 0.f;

#pragma unroll
        for (int ks = 0; ks < 8; ++ks) {
            uint32_t bf[8][2];
#pragma unroll
            for (int j = 0; j < 8; ++j) {
                bf[j][0] = kb[(j * 8 + lq) * KLD + ks * 8 + lr];
                bf[j][1] = kb[(j * 8 + lq) * KLD + ks * 8 + lr + 4];
            }
#pragma unroll
            for (int j = 0; j < 8; ++j)
                mma8(s[j], qa[ks], bf[j]);
        }

        // online softmax; rows lq (r0,r1) and lq+8 (r2,r3)
        float mx0 = NEG_INF, mx1 = NEG_INF;
#pragma unroll
        for (int j = 0; j < 8; ++j) {
            mx0 = fmaxf(mx0, fmaxf(s[j][0], s[j][1]));
            mx1 = fmaxf(mx1, fmaxf(s[j][2], s[j][3]));
        }
        mx0 = fmaxf(mx0, __shfl_xor_sync(0xffffffffu, mx0, 1));
        mx0 = fmaxf(mx0, __shfl_xor_sync(0xffffffffu, mx0, 2));
        mx1 = fmaxf(mx1, __shfl_xor_sync(0xffffffffu, mx1, 1));
        mx1 = fmaxf(mx1, __shfl_xor_sync(0xffffffffu, mx1, 2));

        float mn0 = fmaxf(m_i[0], mx0), mn1 = fmaxf(m_i[1], mx1);
        float c0 = __expf(m_i[0] - mn0), c1 = __expf(m_i[1] - mn1);
        m_i[0] = mn0; m_i[1] = mn1;

        float ls0 = 0.f, ls1 = 0.f;
#pragma unroll
        for (int j = 0; j < 8; ++j) {
            float p0 = __expf(s[j][0] - mn0);
            float p1 = __expf(s[j][1] - mn0);
            float p2 = __expf(s[j][2] - mn1);
            float p3 = __expf(s[j][3] - mn1);
            ls0 += p0 + p1;
            ls1 += p2 + p3;
            Pn[(m0 + lq) * PLD + j * 8 + 2 * lr]     = f2tf32(p0);
            Pn[(m0 + lq) * PLD + j * 8 + 2 * lr + 1] = f2tf32(p1);
            Pn[(m0 + lq + 8) * PLD + j * 8 + 2 * lr]     = f2tf32(p2);
            Pn[(m0 + lq + 8) * PLD + j * 8 + 2 * lr + 1] = f2tf32(p3);
        }
        ls0 += __shfl_xor_sync(0xffffffffu, ls0, 1);
        ls0 += __shfl_xor_sync(0xffffffffu, ls0, 2);
        ls1 += __shfl_xor_sync(0xffffffffu, ls1, 1);
        ls1 += __shfl_xor_sync(0xffffffffu, ls1, 2);
        l_i[0] = l_i[0] * c0 + ls0;
        l_i[1] = l_i[1] * c1 + ls1;

#pragma unroll
        for (int j = 0; j < 8; ++j) {
            oacc[j][0] *= c0; oacc[j][1] *= c0;
            oacc[j][2] *= c1; oacc[j][3] *= c1;
        }
        __syncwarp();

        // O += P V
#pragma unroll
        for (int ks = 0; ks < 8; ++ks) {
            uint32_t pa4[4];
            pa4[0] = Pn[(m0 + lq) * PLD + ks * 8 + lr];
            pa4[1] = Pn[(m0 + lq + 8) * PLD + ks * 8 + lr];
            pa4[2] = Pn[(m0 + lq) * PLD + ks * 8 + lr + 4];
            pa4[3] = Pn[(m0 + lq + 8) * PLD + ks * 8 + lr + 4];
            uint32_t bf[8][2];
#pragma unroll
            for (int j = 0; j < 8; ++j) {
                bf[j][0] = vb[(ks * 8 + lr) * VLD + j * 8 + lq];
                bf[j][1] = vb[(ks * 8 + lr + 4) * VLD + j * 8 + lq];
            }
#pragma unroll
            for (int j = 0; j < 8; ++j)
                mma8(oacc[j], pa4, bf[j]);
        }

        if (kt + 1 < NN / 64) CP_WAIT0();
        __syncthreads();
        st ^= 1;
    }

    // normalize + store
    float inv0 = 1.0f / l_i[0], inv1 = 1.0f / l_i[1];
#pragma unroll
    for (int j = 0; j < 8; ++j) {
        float2 r0 = {oacc[j][0] * inv0, oacc[j][1] * inv0};
        float2 r1 = {oacc[j][2] * inv1, oacc[j][3] * inv1};
        *(float2*)(o + (size_t)(qbase + m0 + lq) * ED + hoff + j * 8 + 2 * lr) = r0;
        *(float2*)(o + (size_t)(qbase + m0 + lq + 8) * ED + hoff + j * 8 + 2 * lr) = r1;
    }
}

// ---------------------------------------------------------------------------
// Host launcher
// ---------------------------------------------------------------------------
extern "C" void kernel_launch(void* const* d_in, const int* in_sizes, int n_in,
                              void* d_out, int out_size)
{
    const float* nf   = (const float*)d_in[0];
    const int*   ei   = (const int*)  d_in[1];
    const int*   ct   = (const int*)  d_in[2];
    const float* Wq   = (const float*)d_in[3];
    const float* bq   = (const float*)d_in[4];
    const float* Wk   = (const float*)d_in[5];
    const float* bk   = (const float*)d_in[6];
    const float* Wv   = (const float*)d_in[7];
    const float* bv   = (const float*)d_in[8];
    const float* bio  = (const float*)d_in[9];
    const float* cemb = (const float*)d_in[10];
    const float* ipw  = (const float*)d_in[11];
    const float* ipb  = (const float*)d_in[12];
    const float* outw = (const float*)d_in[13];
    const float* outb = (const float*)d_in[14];

    float* out      = (float*)d_out;
    float* attended = out;                                    // [4096,512]
    float* attn     = out + (size_t)NN * ED;                  // [4096,4096]
    float* phase    = attn + (size_t)NN * NN;                 // [4096,512]
    float* coh      = phase + (size_t)NN * ED;                // scalar

    const int ne = in_sizes[1] / 2;
    const size_t NS = (size_t)NN * ED;

    float *Q0, *K0, *QKV, *qkv2, *og, *bioT, *rowent;
    unsigned* msk;
    cudaGetSymbolAddress((void**)&Q0,     g_Q0);
    cudaGetSymbolAddress((void**)&K0,     g_K0);
    cudaGetSymbolAddress((void**)&QKV,    g_QKV);
    cudaGetSymbolAddress((void**)&qkv2,   g_qkv2);
    cudaGetSymbolAddress((void**)&og,     g_o);
    cudaGetSymbolAddress((void**)&bioT,   g_bioT);
    cudaGetSymbolAddress((void**)&msk,    g_mask);
    cudaGetSymbolAddress((void**)&rowent, g_rowent);

    // edge mask
    zero_mask_kernel<<<(NN * MASKW) / 1024, 1024>>>(msk);
    build_mask_kernel<<<(ne + 255) / 256, 256>>>(ei, ne, msk);

    // bio^T for Q-side mixing
    transpose512_kernel<<<dim3(16, 16), dim3(32, 8)>>>(bio, bioT);

    // ---- Q/K chain feeding phase: EXACT fp32, 128x128 tiles, 2 CTA/SM, z-batched ----
    sgemm_nt2<EPI_BIAS><<<dim3(4, 32, 2), 256>>>(nf, Wq, Q0, bq,
                                                 nf, Wk, K0, bk,
                                                 NN, ED, DIN, nullptr, nullptr);
    sgemm_nt2<EPI_CE><<<dim3(4, 32, 2), 256>>>(Q0, bioT, QKV, nullptr,
                                               K0, bio, QKV + NS, nullptr,
                                               NN, ED, ED, ct, cemb);

    // V projection (3xTF32, feeds only attended)
    gemm_tf32<64, 128, EPI_BIAS, true, false><<<dim3(4, 64), 256>>>(
        nf, 0, Wv, 0, QKV + 2 * NS, 0, NN, ED, DIN,
        bv, 0, nullptr, nullptr, nullptr, 0.f);

    // phase = atan2(Kf, Qf)  (exact inputs)
    phase_kernel<<<(NN * ED) / 1024, 1024>>>(QKV, QKV + NS, phase);

    // masked scores -> attn region (1xTF32):  Qf @ Kf^T / sqrt(512), -1e9 off-edge
    gemm_tf32<128, 128, EPI_MASK, false, false><<<dim3(32, 32), 256>>>(
        QKV, 0, QKV + NS, 0, attn, 0, NN, NN, ED,
        nullptr, 0, nullptr, nullptr, msk, 0.044194173824159216f);

    // row softmax in-place + per-row entropy, then coherence
    softmax_row_kernel<<<NN, 256>>>(attn, rowent);
    reduce_entropy_kernel<<<1, 1024>>>(rowent, coh);

    // in_proj (3xTF32, batched z=3), epilogue stores RN-tf32 bits for flash
    gemm_tf32<64, 128, EPI_BIAS, true, true><<<dim3(4, 64, 3), 256>>>(
        QKV, (long long)NS, ipw, (long long)ED * ED, qkv2, (long long)NS,
        NN, ED, ED, ipb, (long long)ED,
        nullptr, nullptr, nullptr, 0.f);

    // flash MHA per head (tf32 tensor cores, cp.async raw RN bits, 2 CTA/SM)
    const int mha_smem = (128 * PLD + 2 * KTS + 2 * VTS) * 4;   // 114688 B
    cudaFuncSetAttribute(flash_mha_tf32, cudaFuncAttributeMaxDynamicSharedMemorySize, mha_smem);
    flash_mha_tf32<<<dim3(NN / 128, NHEAD), 256, mha_smem>>>(qkv2, qkv2 + NS, qkv2 + 2 * NS, og);

    // output projection (3xTF32)
    gemm_tf32<64, 128, EPI_BIAS, true, false><<<dim3(4, 64), 256>>>(
        og, 0, outw, 0, attended, 0, NN, ED, ED,
        outb, 0, nullptr, nullptr, nullptr, 0.f);
}

// round 17
// speedup vs baseline: 1.0971x; 1.0048x over previous
#include <cuda_runtime.h>
#include <math.h>
#include <stdint.h>

// ---------------------------------------------------------------------------
// Problem constants
// ---------------------------------------------------------------------------
#define NN 4096          // nodes
#define DIN 256          // input dim
#define ED 512           // quantum dim
#define NHEAD 8
#define HD 64
#define MASKW 128        // 4096/32 words per row

#define NEG_INF (__int_as_float(0xff800000))

// ---------------------------------------------------------------------------
// Scratch (device globals; no allocation allowed)
// ---------------------------------------------------------------------------
__device__ float    g_Q0[(size_t)NN * ED];
__device__ float    g_K0[(size_t)NN * ED];
__device__ float    g_QKV[(size_t)3 * NN * ED];   // Qfinal, Kfinal, V
__device__ float    g_qkv2[(size_t)3 * NN * ED];  // q, k, v after in_proj (tf32-RN bits)
__device__ float    g_o[(size_t)NN * ED];
__device__ float    g_bioT[(size_t)ED * ED];
__device__ unsigned g_mask[(size_t)NN * MASKW];
__device__ float    g_rowent[NN];

// ---------------------------------------------------------------------------
// Helpers
// ---------------------------------------------------------------------------
__device__ __forceinline__ float warp_red_sum(float v) {
#pragma unroll
    for (int o = 16; o; o >>= 1) v += __shfl_xor_sync(0xffffffffu, v, o);
    return v;
}
__device__ __forceinline__ float warp_red_max(float v) {
#pragma unroll
    for (int o = 16; o; o >>= 1) v = fmaxf(v, __shfl_xor_sync(0xffffffffu, v, o));
    return v;
}

__device__ __forceinline__ uint32_t f2tf32(float x) {
    uint32_t u;
    asm("cvt.rna.tf32.f32 %0, %1;" : "=r"(u) : "f"(x));
    return u;
}

__device__ __forceinline__ void mma8(float* c, const uint32_t* a, const uint32_t* b) {
    asm volatile(
        "mma.sync.aligned.m16n8k8.row.col.f32.tf32.tf32.f32 "
        "{%0,%1,%2,%3}, {%4,%5,%6,%7}, {%8,%9}, {%0,%1,%2,%3};"
        : "+f"(c[0]), "+f"(c[1]), "+f"(c[2]), "+f"(c[3])
        : "r"(a[0]), "r"(a[1]), "r"(a[2]), "r"(a[3]), "r"(b[0]), "r"(b[1]));
}

__device__ __forceinline__ void cp_async16(uint32_t saddr, const void* gaddr) {
    asm volatile("cp.async.cg.shared.global [%0], [%1], 16;" :: "r"(saddr), "l"(gaddr));
}
#define CP_COMMIT() asm volatile("cp.async.commit_group;" ::: "memory")
#define CP_WAIT0()  asm volatile("cp.async.wait_group 0;" ::: "memory")

// ---------------------------------------------------------------------------
// Mask build
// ---------------------------------------------------------------------------
__global__ void zero_mask_kernel(unsigned* __restrict__ m) {
    m[(size_t)blockIdx.x * 1024 + threadIdx.x] = 0u;
}

__global__ void build_mask_kernel(const int* __restrict__ ei, int ne,
                                  unsigned* __restrict__ m) {
    int idx = blockIdx.x * blockDim.x + threadIdx.x;
    if (idx < ne) {
        int r = ei[idx];
        int c = ei[ne + idx];
        atomicOr(&m[(size_t)r * MASKW + (c >> 5)], 1u << (c & 31));
    }
}

// ---------------------------------------------------------------------------
// 512x512 transpose (bio -> bioT)
// ---------------------------------------------------------------------------
__global__ void transpose512_kernel(const float* __restrict__ in, float* __restrict__ out) {
    __shared__ float tile[32][33];
    int bx = blockIdx.x * 32, by = blockIdx.y * 32;
    int tx = threadIdx.x, ty = threadIdx.y;
#pragma unroll
    for (int j = 0; j < 32; j += 8)
        tile[ty + j][tx] = in[(size_t)(by + ty + j) * ED + bx + tx];
    __syncthreads();
#pragma unroll
    for (int j = 0; j < 32; j += 8)
        out[(size_t)(bx + ty + j) * ED + by + tx] = tile[tx][ty + j];
}

// ---------------------------------------------------------------------------
// fp32 SGEMM (NT), exact: C[M,N] = A[M,K] * B[N,K]^T  (+ epilogue)
// Q/K chain only (zero precision budget for atan2-phase).
// 128x128 tile, 8x8 microtile, __launch_bounds__(256,2) caps regs at 128 so
// two CTAs co-reside (measured R15: regs=128, occ 21.9%, pair 80.4us).
// z-batched: blockIdx.z selects {A0,B0,C0,bias0} / {A1,B1,C1,bias1}.
// ---------------------------------------------------------------------------
#define BM 128
#define BN 128
#define BK 16

enum { EPI_BIAS = 0, EPI_CE = 1, EPI_MASK = 2 };

template <int EPI>
__global__ void __launch_bounds__(256, 2)
sgemm_nt2(const float* __restrict__ A0, const float* __restrict__ B0,
          float* __restrict__ C0, const float* __restrict__ bias0,
          const float* __restrict__ A1, const float* __restrict__ B1,
          float* __restrict__ C1, const float* __restrict__ bias1,
          int M, int N, int K,
          const int* __restrict__ ct,
          const float* __restrict__ cemb)
{
    const float* A    = blockIdx.z ? A1 : A0;
    const float* B    = blockIdx.z ? B1 : B0;
    float*       C    = blockIdx.z ? C1 : C0;
    const float* bias = blockIdx.z ? bias1 : bias0;

    __shared__ float As[2][BK][BM];
    __shared__ float Bs[2][BK][BN];

    const int tid = threadIdx.x;
    const int tx = tid & 15, ty = tid >> 4;
    const int bm = blockIdx.y * BM, bn = blockIdx.x * BN;

    const int lrow = tid >> 2;            // 0..63
    const int lc4  = (tid & 3) * 4;       // 0,4,8,12

    float acc[8][8];
#pragma unroll
    for (int i = 0; i < 8; ++i)
#pragma unroll
        for (int j = 0; j < 8; ++j) acc[i][j] = 0.f;

    float4 pa[2], pb[2];

    auto ldg = [&](int k0) {
#pragma unroll
        for (int t = 0; t < 2; ++t) {
            int row = lrow + t * 64;
            pa[t] = *(const float4*)(A + (size_t)(bm + row) * K + k0 + lc4);
            pb[t] = *(const float4*)(B + (size_t)(bn + row) * K + k0 + lc4);
        }
    };
    auto sts = [&](int st) {
#pragma unroll
        for (int t = 0; t < 2; ++t) {
            int row = lrow + t * 64;
            As[st][lc4 + 0][row] = pa[t].x; As[st][lc4 + 1][row] = pa[t].y;
            As[st][lc4 + 2][row] = pa[t].z; As[st][lc4 + 3][row] = pa[t].w;
            Bs[st][lc4 + 0][row] = pb[t].x; Bs[st][lc4 + 1][row] = pb[t].y;
            Bs[st][lc4 + 2][row] = pb[t].z; Bs[st][lc4 + 3][row] = pb[t].w;
        }
    };

    ldg(0);
    sts(0);
    __syncthreads();

    const int nk = K / BK;
    int st = 0;
    for (int kt = 0; kt < nk; ++kt) {
        if (kt + 1 < nk) ldg((kt + 1) * BK);
#pragma unroll
        for (int kk = 0; kk < BK; ++kk) {
            float4 a0 = *(const float4*)&As[st][kk][ty * 8];
            float4 a1 = *(const float4*)&As[st][kk][ty * 8 + 4];
            float4 b0 = *(const float4*)&Bs[st][kk][tx * 8];
            float4 b1 = *(const float4*)&Bs[st][kk][tx * 8 + 4];
            float av[8] = {a0.x, a0.y, a0.z, a0.w, a1.x, a1.y, a1.z, a1.w};
            float bv[8] = {b0.x, b0.y, b0.z, b0.w, b1.x, b1.y, b1.z, b1.w};
#pragma unroll
            for (int i = 0; i < 8; ++i)
#pragma unroll
                for (int j = 0; j < 8; ++j)
                    acc[i][j] += av[i] * bv[j];
        }
        if (kt + 1 < nk) sts(st ^ 1);
        __syncthreads();
        st ^= 1;
    }

#pragma unroll
    for (int i = 0; i < 8; ++i) {
        int gm = bm + ty * 8 + i;
#pragma unroll
        for (int j = 0; j < 8; ++j) {
            int gn = bn + tx * 8 + j;
            float v = acc[i][j];
            if (EPI == EPI_BIAS) {
                v += bias[gn];
            } else {
                v += 0.1f * cemb[(size_t)ct[gm] * N + gn];
            }
            C[(size_t)gm * N + gn] = v;
        }
    }
}

// ---------------------------------------------------------------------------
// tf32 tensor-core GEMM (NT):  C[M,N] = A[M,K] * B[N,K]^T  (+ epilogue)
// SPLIT=true: 3xTF32 (near-fp32). SPLIT=false: single tf32, double-buffered.
// CVT=true: store f2tf32(result) bits (producer-side RN conversion for the
// flash-MHA consumer, which then cp.asyncs raw bits).
// ---------------------------------------------------------------------------
template <int TBM, int TBN, int EPI, bool SPLIT, bool CVT>
__global__ void __launch_bounds__(256)
gemm_tf32(const float* __restrict__ A, long long sAz,
          const float* __restrict__ B, long long sBz,
          float* __restrict__ C, long long sCz,
          int M, int N, int K,
          const float* __restrict__ bias, long long sbz,
          const int* __restrict__ ct,
          const float* __restrict__ cemb,
          const unsigned* __restrict__ mask,
          float scale)
{
    constexpr int LDA = TBM + 8;
    constexpr int LDB = TBN + 8;
    constexpr int AF4 = (TBM * 16) / (4 * 256);
    constexpr int BF4 = (TBN * 16) / (4 * 256);
    constexpr int WM = TBM / 4, WN = TBN / 2;
    constexpr int MF = WM / 16, NF = WN / 8;
    constexpr int NC = SPLIT ? 2 : 1;
    constexpr int NBUF = SPLIT ? 1 : 2;

    __shared__ uint32_t As[NBUF][NC][16][LDA];
    __shared__ uint32_t Bs[NBUF][NC][16][LDB];

    A += (size_t)blockIdx.z * sAz;
    B += (size_t)blockIdx.z * sBz;
    C += (size_t)blockIdx.z * sCz;
    if (bias) bias += (size_t)blockIdx.z * sbz;

    const int tid = threadIdx.x;
    const int lane = tid & 31, wid = tid >> 5;
    const int wm = wid & 3, wn = wid >> 2;
    const int bm = blockIdx.y * TBM, bn = blockIdx.x * TBN;
    const int lq = lane >> 2, lr = lane & 3;

    float c[MF][NF][4];
#pragma unroll
    for (int i = 0; i < MF; ++i)
#pragma unroll
        for (int j = 0; j < NF; ++j)
#pragma unroll
            for (int r = 0; r < 4; ++r) c[i][j][r] = 0.f;

    float4 pa[AF4], pb[BF4];

    auto store_a = [&](int st) {
#pragma unroll
        for (int t = 0; t < AF4; ++t) {
            int f = tid + t * 256, m = f >> 2, k4 = (f & 3) * 4;
            float xs[4] = {pa[t].x, pa[t].y, pa[t].z, pa[t].w};
#pragma unroll
            for (int e = 0; e < 4; ++e) {
                uint32_t h = f2tf32(xs[e]);
                As[st][0][k4 + e][m] = h;
                if (SPLIT)
                    As[st][1][k4 + e][m] = f2tf32(xs[e] - __uint_as_float(h));
            }
        }
    };
    auto store_b = [&](int st) {
#pragma unroll
        for (int t = 0; t < BF4; ++t) {
            int f = tid + t * 256, n = f >> 2, k4 = (f & 3) * 4;
            float xs[4] = {pb[t].x, pb[t].y, pb[t].z, pb[t].w};
#pragma unroll
            for (int e = 0; e < 4; ++e) {
                uint32_t h = f2tf32(xs[e]);
                Bs[st][0][k4 + e][n] = h;
                if (SPLIT)
                    Bs[st][1][k4 + e][n] = f2tf32(xs[e] - __uint_as_float(h));
            }
        }
    };
    auto load_ab = [&](int k0) {
#pragma unroll
        for (int t = 0; t < AF4; ++t) {
            int f = tid + t * 256;
            pa[t] = *(const float4*)(A + (size_t)(bm + (f >> 2)) * K + k0 + (f & 3) * 4);
        }
#pragma unroll
        for (int t = 0; t < BF4; ++t) {
            int f = tid + t * 256;
            pb[t] = *(const float4*)(B + (size_t)(bn + (f >> 2)) * K + k0 + (f & 3) * 4);
        }
    };
    auto compute = [&](int st) {
#pragma unroll
        for (int ks = 0; ks < 16; ks += 8) {
            uint32_t af[MF][NC][4], bf[NF][NC][2];
#pragma unroll
            for (int i = 0; i < MF; ++i) {
                int m0 = wm * WM + i * 16;
#pragma unroll
                for (int cc = 0; cc < NC; ++cc) {
                    af[i][cc][0] = As[st][cc][ks + lr][m0 + lq];
                    af[i][cc][1] = As[st][cc][ks + lr][m0 + lq + 8];
                    af[i][cc][2] = As[st][cc][ks + lr + 4][m0 + lq];
                    af[i][cc][3] = As[st][cc][ks + lr + 4][m0 + lq + 8];
                }
            }
#pragma unroll
            for (int j = 0; j < NF; ++j) {
                int n0 = wn * WN + j * 8;
#pragma unroll
                for (int cc = 0; cc < NC; ++cc) {
                    bf[j][cc][0] = Bs[st][cc][ks + lr][n0 + lq];
                    bf[j][cc][1] = Bs[st][cc][ks + lr + 4][n0 + lq];
                }
            }
#pragma unroll
            for (int i = 0; i < MF; ++i)
#pragma unroll
                for (int j = 0; j < NF; ++j) {
                    mma8(c[i][j], af[i][0], bf[j][0]);
                    if (SPLIT) {
                        mma8(c[i][j], af[i][0], bf[j][1]);
                        mma8(c[i][j], af[i][1], bf[j][0]);
                    }
                }
        }
    };

    const int nk = K >> 4;

    if (!SPLIT) {
        load_ab(0);
        store_a(0); store_b(0);
        __syncthreads();
        int st = 0;
        for (int kt = 0; kt < nk; ++kt) {
            if (kt + 1 < nk) load_ab((kt + 1) << 4);
            compute(st);
            if (kt + 1 < nk) { store_a(st ^ 1); store_b(st ^ 1); }
            __syncthreads();
            st ^= 1;
        }
    } else {
        load_ab(0);
        store_a(0); store_b(0);
        __syncthreads();
        for (int kt = 0; kt < nk; ++kt) {
            if (kt + 1 < nk) load_ab((kt + 1) << 4);
            compute(0);
            __syncthreads();
            if (kt + 1 < nk) {
                store_a(0); store_b(0);
                __syncthreads();
            }
        }
    }

#pragma unroll
    for (int i = 0; i < MF; ++i) {
        int gm = bm + wm * WM + i * 16 + lq;
        int t0 = 0, t1 = 0;
        if (EPI == EPI_CE) { t0 = ct[gm]; t1 = ct[gm + 8]; }
#pragma unroll
        for (int j = 0; j < NF; ++j) {
            int gn = bn + wn * WN + j * 8 + lr * 2;
            float v00 = c[i][j][0], v01 = c[i][j][1];
            float v10 = c[i][j][2], v11 = c[i][j][3];
            if (EPI == EPI_BIAS) {
                float b0 = bias[gn], b1 = bias[gn + 1];
                v00 += b0; v01 += b1; v10 += b0; v11 += b1;
            } else if (EPI == EPI_CE) {
                v00 += 0.1f * cemb[(size_t)t0 * N + gn];
                v01 += 0.1f * cemb[(size_t)t0 * N + gn + 1];
                v10 += 0.1f * cemb[(size_t)t1 * N + gn];
                v11 += 0.1f * cemb[(size_t)t1 * N + gn + 1];
            } else {
                unsigned w0 = mask[(size_t)gm * MASKW + (gn >> 5)];
                unsigned w1 = mask[(size_t)(gm + 8) * MASKW + (gn >> 5)];
                v00 = ((w0 >> (gn & 31)) & 1u) ? v00 * scale : -1e9f;
                v01 = ((w0 >> ((gn + 1) & 31)) & 1u) ? v01 * scale : -1e9f;
                v10 = ((w1 >> (gn & 31)) & 1u) ? v10 * scale : -1e9f;
                v11 = ((w1 >> ((gn + 1) & 31)) & 1u) ? v11 * scale : -1e9f;
            }
            if (CVT) {
                v00 = __uint_as_float(f2tf32(v00));
                v01 = __uint_as_float(f2tf32(v01));
                v10 = __uint_as_float(f2tf32(v10));
                v11 = __uint_as_float(f2tf32(v11));
            }
            float2 r0 = {v00, v01}, r1 = {v10, v11};
            *(float2*)(C + (size_t)gm * N + gn) = r0;
            *(float2*)(C + (size_t)(gm + 8) * N + gn) = r1;
        }
    }
}

// ---------------------------------------------------------------------------
// phase = atan2(K, Q) elementwise
// ---------------------------------------------------------------------------
__global__ void phase_kernel(const float* __restrict__ Q, const float* __restrict__ K,
                             float* __restrict__ phase) {
    size_t i = (size_t)blockIdx.x * blockDim.x + threadIdx.x;
    phase[i] = atan2f(K[i], Q[i]);
}

// ---------------------------------------------------------------------------
// Row softmax over masked scores (in-place on attn region) + per-row entropy.
// Analytic entropy: with p_i = e_i/S, e_i = exp(x_i - mx),
//   sum p_i log p_i = (sum e_i (x_i - mx))/S - log S   -> ONE logf per row.
// v2 sync structure: separate red_s/red_w arrays, 3 uniform barriers total
// (fewer than the original 5) — no smem reuse across barrier phases.
// ---------------------------------------------------------------------------
__global__ void __launch_bounds__(256)
softmax_row_kernel(float* __restrict__ attn, float* __restrict__ row_ent) {
    __shared__ float red_s[8];
    __shared__ float red_w[8];
    __shared__ float sh_mx;
    __shared__ float sh_S;
    const int tid = threadIdx.x;
    const int wid = tid >> 5, lane = tid & 31;
    float* p = attn + (size_t)blockIdx.x * NN;

    float4 x[4];
#pragma unroll
    for (int t = 0; t < 4; ++t)
        x[t] = *(const float4*)(p + t * 1024 + tid * 4);

    // --- row max (red_s used once, then never reused before next barrier-pair) ---
    float mx = NEG_INF;
#pragma unroll
    for (int t = 0; t < 4; ++t)
        mx = fmaxf(fmaxf(fmaxf(mx, x[t].x), fmaxf(x[t].y, x[t].z)), x[t].w);
    mx = warp_red_max(mx);
    if (lane == 0) red_s[wid] = mx;
    __syncthreads();                                   // (1)
    if (wid == 0) {
        float v = (lane < 8) ? red_s[lane] : NEG_INF;
        v = warp_red_max(v);
        if (lane == 0) sh_mx = v;
    }
    __syncthreads();                                   // (2) sh_mx visible; wid0 reads of red_s done
    mx = sh_mx;

    // --- exp, sum S, weighted sum W = sum e*d ---
    float e[16];
    float s = 0.f, w = 0.f;
#pragma unroll
    for (int t = 0; t < 4; ++t) {
        float d0 = x[t].x - mx, d1 = x[t].y - mx, d2 = x[t].z - mx, d3 = x[t].w - mx;
        float e0 = __expf(d0), e1 = __expf(d1), e2 = __expf(d2), e3 = __expf(d3);
        e[t * 4 + 0] = e0; e[t * 4 + 1] = e1; e[t * 4 + 2] = e2; e[t * 4 + 3] = e3;
        s += e0 + e1 + e2 + e3;
        w += e0 * d0 + e1 * d1 + e2 * d2 + e3 * d3;
    }
    s = warp_red_sum(s);
    w = warp_red_sum(w);
    if (lane == 0) { red_s[wid] = s; red_w[wid] = w; }
    __syncthreads();                                   // (3)
    if (wid == 0) {
        float vs = (lane < 8) ? red_s[lane] : 0.f;
        float vw = (lane < 8) ? red_w[lane] : 0.f;
        vs = warp_red_sum(vs);
        vw = warp_red_sum(vw);
        if (lane == 0) {
            sh_S = vs;
            row_ent[blockIdx.x] = vw / vs - logf(vs);  // sum p log p
        }
    }
    __syncthreads();                                   // (4) sh_S visible
    const float inv = 1.0f / sh_S;

    // normalize + store
#pragma unroll
    for (int t = 0; t < 4; ++t) {
        float4 r;
        r.x = e[t * 4 + 0] * inv;
        r.y = e[t * 4 + 1] * inv;
        r.z = e[t * 4 + 2] * inv;
        r.w = e[t * 4 + 3] * inv;
        *(float4*)(p + t * 1024 + tid * 4) = r;
    }
}

__global__ void reduce_entropy_kernel(const float* __restrict__ row_ent,
                                      float* __restrict__ coh) {
    __shared__ float red[32];
    int tid = threadIdx.x, lane = tid & 31, wid = tid >> 5;
    float v = row_ent[tid] + row_ent[tid + 1024] + row_ent[tid + 2048] + row_ent[tid + 3072];
    v = warp_red_sum(v);
    if (lane == 0) red[wid] = v;
    __syncthreads();
    if (wid == 0) {
        float s = red[lane];
        s = warp_red_sum(s);
        if (lane == 0) {
            float entropy = -s;
            *coh = 1.0f - entropy / logf((float)NN);
        }
    }
}

// ---------------------------------------------------------------------------
// Flash MHA on tf32 tensor cores: softmax(q k^T / 8) v, per head.
// v4: inputs (qkv2) are ALREADY RN-tf32 (converted in the in_proj epilogue),
// so K/V cp.async raw bits straight into smem (full pipeline, no CVT cost,
// full RN accuracy). Q scaled by exact 1/8 (tf32-closed). P reuses Q staging.
// 112 KB smem -> 2 CTA/SM -> one wave.
// ---------------------------------------------------------------------------
#define PLD 76
#define KLD 76
#define VLD 72
#define KTS (64 * KLD)
#define VTS (64 * VLD)

__global__ void __launch_bounds__(256, 2)
flash_mha_tf32(const float* __restrict__ q, const float* __restrict__ k,
               const float* __restrict__ v, float* __restrict__ o)
{
    extern __shared__ uint32_t sm[];
    uint32_t* Pn = sm;                    // [128][PLD]  (Q staging, then P)
    uint32_t* Ks = Pn + 128 * PLD;        // [2][64][KLD] RN-tf32 bits
    uint32_t* Vs = Ks + 2 * KTS;          // [2][64][VLD] RN-tf32 bits

    const int tid = threadIdx.x;
    const int lane = tid & 31, wid = tid >> 5;
    const int lq = lane >> 2, lr = lane & 3;
    const int qbase = blockIdx.x * 128;
    const int hoff = blockIdx.y * HD;
    const int m0 = wid * 16;

    const uint32_t ks_base = (uint32_t)__cvta_generic_to_shared(Ks);
    const uint32_t vs_base = (uint32_t)__cvta_generic_to_shared(Vs);

    // Q (already tf32) -> smem staging, scaled by exact 1/8 (exponent shift)
#pragma unroll
    for (int t = 0; t < 8; ++t) {
        int f = tid + t * 256;                  // 0..2047 float4s
        int row = f >> 4, c4 = (f & 15) * 4;
        float4 val = *(const float4*)(q + (size_t)(qbase + row) * ED + hoff + c4);
        Pn[row * PLD + c4 + 0] = __float_as_uint(0.125f * val.x);
        Pn[row * PLD + c4 + 1] = __float_as_uint(0.125f * val.y);
        Pn[row * PLD + c4 + 2] = __float_as_uint(0.125f * val.z);
        Pn[row * PLD + c4 + 3] = __float_as_uint(0.125f * val.w);
    }
    __syncthreads();

    // Q fragments to registers
    uint32_t qa[8][4];
#pragma unroll
    for (int ks = 0; ks < 8; ++ks) {
        qa[ks][0] = Pn[(m0 + lq) * PLD + ks * 8 + lr];
        qa[ks][1] = Pn[(m0 + lq + 8) * PLD + ks * 8 + lr];
        qa[ks][2] = Pn[(m0 + lq) * PLD + ks * 8 + lr + 4];
        qa[ks][3] = Pn[(m0 + lq + 8) * PLD + ks * 8 + lr + 4];
    }

    auto prefetch = [&](int kt, int stg) {
        const float* kg = k + (size_t)(kt * 64) * ED + hoff;
        const float* vg = v + (size_t)(kt * 64) * ED + hoff;
        uint32_t kb = ks_base + (uint32_t)(stg * KTS) * 4u;
        uint32_t vb = vs_base + (uint32_t)(stg * VTS) * 4u;
#pragma unroll
        for (int t = 0; t < 4; ++t) {
            int f = tid + t * 256;              // 0..1023 float4s
            int row = f >> 4, c4 = (f & 15) * 4;
            cp_async16(kb + (uint32_t)(row * KLD + c4) * 4u, kg + (size_t)row * ED + c4);
            cp_async16(vb + (uint32_t)(row * VLD + c4) * 4u, vg + (size_t)row * ED + c4);
        }
    };

    float m_i[2] = {NEG_INF, NEG_INF};
    float l_i[2] = {0.f, 0.f};
    float oacc[8][4];
#pragma unroll
    for (int j = 0; j < 8; ++j)
#pragma unroll
        for (int r = 0; r < 4; ++r) oacc[j][r] = 0.f;

    prefetch(0, 0);
    CP_COMMIT();
    CP_WAIT0();
    __syncthreads();   // stage 0 ready; also orders Q-fragment reads before P writes

    int st = 0;
    for (int kt = 0; kt < NN / 64; ++kt) {
        if (kt + 1 < NN / 64) { prefetch(kt + 1, st ^ 1); CP_COMMIT(); }

        const uint32_t* kb = Ks + st * KTS;
        const uint32_t* vb = Vs + st * VTS;

        // S = Q K^T (scale folded into Q)
        float s[8][4];
#pragma unroll
        for (int j = 0; j < 8; ++j)
#pragma unroll
            for (int r = 0; r < 4; ++r) s[j][r] = 0.f;

#pragma unroll
        for (int ks = 0; ks < 8; ++ks) {
            uint32_t bf[8][2];
#pragma unroll
            for (int j = 0; j < 8; ++j) {
                bf[j][0] = kb[(j * 8 + lq) * KLD + ks * 8 + lr];
                bf[j][1] = kb[(j * 8 + lq) * KLD + ks * 8 + lr + 4];
            }
#pragma unroll
            for (int j = 0; j < 8; ++j)
                mma8(s[j], qa[ks], bf[j]);
        }

        // online softmax; rows lq (r0,r1) and lq+8 (r2,r3)
        float mx0 = NEG_INF, mx1 = NEG_INF;
#pragma unroll
        for (int j = 0; j < 8; ++j) {
            mx0 = fmaxf(mx0, fmaxf(s[j][0], s[j][1]));
            mx1 = fmaxf(mx1, fmaxf(s[j][2], s[j][3]));
        }
        mx0 = fmaxf(mx0, __shfl_xor_sync(0xffffffffu, mx0, 1));
        mx0 = fmaxf(mx0, __shfl_xor_sync(0xffffffffu, mx0, 2));
        mx1 = fmaxf(mx1, __shfl_xor_sync(0xffffffffu, mx1, 1));
        mx1 = fmaxf(mx1, __shfl_xor_sync(0xffffffffu, mx1, 2));

        float mn0 = fmaxf(m_i[0], mx0), mn1 = fmaxf(m_i[1], mx1);
        float c0 = __expf(m_i[0] - mn0), c1 = __expf(m_i[1] - mn1);
        m_i[0] = mn0; m_i[1] = mn1;

        float ls0 = 0.f, ls1 = 0.f;
#pragma unroll
        for (int j = 0; j < 8; ++j) {
            float p0 = __expf(s[j][0] - mn0);
            float p1 = __expf(s[j][1] - mn0);
            float p2 = __expf(s[j][2] - mn1);
            float p3 = __expf(s[j][3] - mn1);
            ls0 += p0 + p1;
            ls1 += p2 + p3;
            Pn[(m0 + lq) * PLD + j * 8 + 2 * lr]     = f2tf32(p0);
            Pn[(m0 + lq) * PLD + j * 8 + 2 * lr + 1] = f2tf32(p1);
            Pn[(m0 + lq + 8) * PLD + j * 8 + 2 * lr]     = f2tf32(p2);
            Pn[(m0 + lq + 8) * PLD + j * 8 + 2 * lr + 1] = f2tf32(p3);
        }
        ls0 += __shfl_xor_sync(0xffffffffu, ls0, 1);
        ls0 += __shfl_xor_sync(0xffffffffu, ls0, 2);
        ls1 += __shfl_xor_sync(0xffffffffu, ls1, 1);
        ls1 += __shfl_xor_sync(0xffffffffu, ls1, 2);
        l_i[0] = l_i[0] * c0 + ls0;
        l_i[1] = l_i[1] * c1 + ls1;

#pragma unroll
        for (int j = 0; j < 8; ++j) {
            oacc[j][0] *= c0; oacc[j][1] *= c0;
            oacc[j][2] *= c1; oacc[j][3] *= c1;
        }
        __syncwarp();

        // O += P V
#pragma unroll
        for (int ks = 0; ks < 8; ++ks) {
            uint32_t pa4[4];
            pa4[0] = Pn[(m0 + lq) * PLD + ks * 8 + lr];
            pa4[1] = Pn[(m0 + lq + 8) * PLD + ks * 8 + lr];
            pa4[2] = Pn[(m0 + lq) * PLD + ks * 8 + lr + 4];
            pa4[3] = Pn[(m0 + lq + 8) * PLD + ks * 8 + lr + 4];
            uint32_t bf[8][2];
#pragma unroll
            for (int j = 0; j < 8; ++j) {
                bf[j][0] = vb[(ks * 8 + lr) * VLD + j * 8 + lq];
                bf[j][1] = vb[(ks * 8 + lr + 4) * VLD + j * 8 + lq];
            }
#pragma unroll
            for (int j = 0; j < 8; ++j)
                mma8(oacc[j], pa4, bf[j]);
        }

        if (kt + 1 < NN / 64) CP_WAIT0();
        __syncthreads();
        st ^= 1;
    }

    // normalize + store
    float inv0 = 1.0f / l_i[0], inv1 = 1.0f / l_i[1];
#pragma unroll
    for (int j = 0; j < 8; ++j) {
        float2 r0 = {oacc[j][0] * inv0, oacc[j][1] * inv0};
        float2 r1 = {oacc[j][2] * inv1, oacc[j][3] * inv1};
        *(float2*)(o + (size_t)(qbase + m0 + lq) * ED + hoff + j * 8 + 2 * lr) = r0;
        *(float2*)(o + (size_t)(qbase + m0 + lq + 8) * ED + hoff + j * 8 + 2 * lr) = r1;
    }
}

// ---------------------------------------------------------------------------
// Host launcher
// ---------------------------------------------------------------------------
extern "C" void kernel_launch(void* const* d_in, const int* in_sizes, int n_in,
                              void* d_out, int out_size)
{
    const float* nf   = (const float*)d_in[0];
    const int*   ei   = (const int*)  d_in[1];
    const int*   ct   = (const int*)  d_in[2];
    const float* Wq   = (const float*)d_in[3];
    const float* bq   = (const float*)d_in[4];
    const float* Wk   = (const float*)d_in[5];
    const float* bk   = (const float*)d_in[6];
    const float* Wv   = (const float*)d_in[7];
    const float* bv   = (const float*)d_in[8];
    const float* bio  = (const float*)d_in[9];
    const float* cemb = (const float*)d_in[10];
    const float* ipw  = (const float*)d_in[11];
    const float* ipb  = (const float*)d_in[12];
    const float* outw = (const float*)d_in[13];
    const float* outb = (const float*)d_in[14];

    float* out      = (float*)d_out;
    float* attended = out;                                    // [4096,512]
    float* attn     = out + (size_t)NN * ED;                  // [4096,4096]
    float* phase    = attn + (size_t)NN * NN;                 // [4096,512]
    float* coh      = phase + (size_t)NN * ED;                // scalar

    const int ne = in_sizes[1] / 2;
    const size_t NS = (size_t)NN * ED;

    float *Q0, *K0, *QKV, *qkv2, *og, *bioT, *rowent;
    unsigned* msk;
    cudaGetSymbolAddress((void**)&Q0,     g_Q0);
    cudaGetSymbolAddress((void**)&K0,     g_K0);
    cudaGetSymbolAddress((void**)&QKV,    g_QKV);
    cudaGetSymbolAddress((void**)&qkv2,   g_qkv2);
    cudaGetSymbolAddress((void**)&og,     g_o);
    cudaGetSymbolAddress((void**)&bioT,   g_bioT);
    cudaGetSymbolAddress((void**)&msk,    g_mask);
    cudaGetSymbolAddress((void**)&rowent, g_rowent);

    // edge mask
    zero_mask_kernel<<<(NN * MASKW) / 1024, 1024>>>(msk);
    build_mask_kernel<<<(ne + 255) / 256, 256>>>(ei, ne, msk);

    // bio^T for Q-side mixing
    transpose512_kernel<<<dim3(16, 16), dim3(32, 8)>>>(bio, bioT);

    // ---- Q/K chain feeding phase: EXACT fp32, 128x128 tiles, 2 CTA/SM, z-batched ----
    sgemm_nt2<EPI_BIAS><<<dim3(4, 32, 2), 256>>>(nf, Wq, Q0, bq,
                                                 nf, Wk, K0, bk,
                                                 NN, ED, DIN, nullptr, nullptr);
    sgemm_nt2<EPI_CE><<<dim3(4, 32, 2), 256>>>(Q0, bioT, QKV, nullptr,
                                               K0, bio, QKV + NS, nullptr,
                                               NN, ED, ED, ct, cemb);

    // V projection (3xTF32, feeds only attended)
    gemm_tf32<64, 128, EPI_BIAS, true, false><<<dim3(4, 64), 256>>>(
        nf, 0, Wv, 0, QKV + 2 * NS, 0, NN, ED, DIN,
        bv, 0, nullptr, nullptr, nullptr, 0.f);

    // phase = atan2(Kf, Qf)  (exact inputs)
    phase_kernel<<<(NN * ED) / 1024, 1024>>>(QKV, QKV + NS, phase);

    // masked scores -> attn region (1xTF32):  Qf @ Kf^T / sqrt(512), -1e9 off-edge
    gemm_tf32<128, 128, EPI_MASK, false, false><<<dim3(32, 32), 256>>>(
        QKV, 0, QKV + NS, 0, attn, 0, NN, NN, ED,
        nullptr, 0, nullptr, nullptr, msk, 0.044194173824159216f);

    // row softmax in-place + per-row entropy (analytic), then coherence
    softmax_row_kernel<<<NN, 256>>>(attn, rowent);
    reduce_entropy_kernel<<<1, 1024>>>(rowent, coh);

    // in_proj (3xTF32, batched z=3), epilogue stores RN-tf32 bits for flash
    gemm_tf32<64, 128, EPI_BIAS, true, true><<<dim3(4, 64, 3), 256>>>(
        QKV, (long long)NS, ipw, (long long)ED * ED, qkv2, (long long)NS,
        NN, ED, ED, ipb, (long long)ED,
        nullptr, nullptr, nullptr, 0.f);

    // flash MHA per head (tf32 tensor cores, cp.async raw RN bits, 2 CTA/SM)
    const int mha_smem = (128 * PLD + 2 * KTS + 2 * VTS) * 4;   // 114688 B
    cudaFuncSetAttribute(flash_mha_tf32, cudaFuncAttributeMaxDynamicSharedMemorySize, mha_smem);
    flash_mha_tf32<<<dim3(NN / 128, NHEAD), 256, mha_smem>>>(qkv2, qkv2 + NS, qkv2 + 2 * NS, og);

    // output projection (3xTF32)
    gemm_tf32<64, 128, EPI_BIAS, true, false><<<dim3(4, 64), 256>>>(
        og, 0, outw, 0, attended, 0, NN, ED, ED,
        outb, 0, nullptr, nullptr, nullptr, 0.f);
}